// round 2
// baseline (speedup 1.0000x reference)
#include <cuda_runtime.h>

#define D    256
#define DC   32      // d-chunk depth
#define TM   128     // token tile
#define TN   128     // code tile
#define MAXK 2048
#define MAXN 65536

#define COMMIT_COST 0.25f
#define DIV_GAMMA   0.1f
#define EPS_F       1e-8f

typedef unsigned long long ull;

// ---------------- device scratch ----------------
__device__ float g_esq[MAXK];
__device__ float g_rninv[MAXK];
__device__ float g_xsq[MAXN];
__device__ int   g_idx[MAXN];
__device__ float g_counts[MAXK];
__device__ float g_acc[4];   // 0: mse_sum, 1: abs-offdiag sum, 2: rownorm sum

// ---------------- f32x2 packed-FMA helpers ----------------
__device__ __forceinline__ void fma2(ull& c, ull a, ull b) {
    asm("fma.rn.f32x2 %0, %1, %2, %0;" : "+l"(c) : "l"(a), "l"(b));
}
__device__ __forceinline__ float2 up2(ull v) {
    unsigned int lo, hi;
    asm("mov.b64 {%0,%1}, %2;" : "=r"(lo), "=r"(hi) : "l"(v));
    return make_float2(__uint_as_float(lo), __uint_as_float(hi));
}

// ================= tile loaders (packed layouts, no inner-loop packing) =================
// Xd: 128 rows x 32 u64, Xd[m][d] = (x[m][d], x[m][d])  -- stride 32 u64, no swizzle
//     (A-side reads are 16-lane broadcast; conflicts impossible)
__device__ __forceinline__ void load_Xdup(ull* Xd, const float* __restrict__ g,
                                          int d0, int tid) {
    int row  = tid >> 1;
    int half = tid & 1;
    const float4* gx = reinterpret_cast<const float4*>(g + (size_t)row * D + d0 + half * 16);
    ull* dst = Xd + row * 32 + half * 16;
#pragma unroll
    for (int i = 0; i < 4; i++) {
        float4 v = gx[i];
        float4* d4 = reinterpret_cast<float4*>(dst + i * 4);
        d4[0] = make_float4(v.x, v.x, v.y, v.y);
        d4[1] = make_float4(v.z, v.z, v.w, v.w);
    }
}

// Ep: 64 pair-rows x 32 u64, Ep[j][d] = (e[2j][d], e[2j+1][d]),
//     XOR-swizzled within row: u64 index = (d ^ ((j&7)<<2))
__device__ __forceinline__ void load_Epair(ull* Ep, const float* __restrict__ g,
                                           int d0, int tid) {
    int j = tid >> 2;
    int q = tid & 3;
    const float* e0 = g + (size_t)(2 * j) * D + d0;
    const float* e1 = e0 + D;
    ull* base = Ep + j * 32;
    int mj = (j & 7) << 2;
#pragma unroll
    for (int gidx = 0; gidx < 2; gidx++) {
        int dq = (q + 4 * gidx) * 4;              // 0..28 step 4
        float4 a = *reinterpret_cast<const float4*>(e0 + dq);
        float4 b = *reinterpret_cast<const float4*>(e1 + dq);
        float4* d4 = reinterpret_cast<float4*>(base + (dq ^ mj));
        d4[0] = make_float4(a.x, b.x, a.y, b.y);
        d4[1] = make_float4(a.z, b.z, a.w, b.w);
    }
}

// ================= 128x128x32 chunk MMA =================
// acc[mi][pg]: mi -> token rows {4ty+0..3, 64+4ty+0..3}
//              pg -> code pair (n0 + 32*pg + 2*tx, +1)
__device__ __forceinline__ void chunk_mma(const ull* __restrict__ Xd,
                                          const ull* __restrict__ Ep,
                                          int ty, int tx, int mB,
                                          ull acc[8][4]) {
#pragma unroll
    for (int hs = 0; hs < 16; hs++) {             // 2 d per half-step
        ulonglong2 b2[4];
#pragma unroll
        for (int pg = 0; pg < 4; pg++) {
            int row = 16 * pg + tx;
            b2[pg] = *reinterpret_cast<const ulonglong2*>(Ep + row * 32 + ((2 * hs) ^ mB));
        }
#pragma unroll
        for (int mi = 0; mi < 8; mi++) {
            int m = (mi < 4) ? (4 * ty + mi) : (64 + 4 * ty + (mi - 4));
            ulonglong2 a2 = *reinterpret_cast<const ulonglong2*>(Xd + m * 32 + 2 * hs);
            fma2(acc[mi][0], a2.x, b2[0].x);
            fma2(acc[mi][1], a2.x, b2[1].x);
            fma2(acc[mi][2], a2.x, b2[2].x);
            fma2(acc[mi][3], a2.x, b2[3].x);
            fma2(acc[mi][0], a2.y, b2[0].y);
            fma2(acc[mi][1], a2.y, b2[1].y);
            fma2(acc[mi][2], a2.y, b2[2].y);
            fma2(acc[mi][3], a2.y, b2[3].y);
        }
    }
}

// ---------------- k_init ----------------
__global__ void k_init(int K) {
    int i = blockIdx.x * blockDim.x + threadIdx.x;
    if (i < K) g_counts[i] = 0.f;
    if (i < 4) g_acc[i] = 0.f;
}

// ---------------- k_prep: esq, 1/rownorm, sum(rownorm) ----------------
__global__ void k_prep(const float* __restrict__ e, int K) {
    int w    = (blockIdx.x * blockDim.x + threadIdx.x) >> 5;
    int lane = threadIdx.x & 31;
    if (w >= K) return;
    const float4* er = reinterpret_cast<const float4*>(e + (size_t)w * D);
    float4 a = er[lane], b = er[32 + lane];
    float s = __fadd_rn(
        __fadd_rn(__fadd_rn(__fmul_rn(a.x,a.x), __fmul_rn(a.y,a.y)),
                  __fadd_rn(__fmul_rn(a.z,a.z), __fmul_rn(a.w,a.w))),
        __fadd_rn(__fadd_rn(__fmul_rn(b.x,b.x), __fmul_rn(b.y,b.y)),
                  __fadd_rn(__fmul_rn(b.z,b.z), __fmul_rn(b.w,b.w))));
#pragma unroll
    for (int off = 16; off > 0; off >>= 1) s += __shfl_xor_sync(0xffffffffu, s, off);
    if (lane == 0) {
        g_esq[w] = s;
        float rn = sqrtf(s);
        g_rninv[w] = 1.0f / fmaxf(rn, 1e-12f);
        atomicAdd(&g_acc[2], rn);
    }
}

// ---------------- k_xsq ----------------
__global__ void k_xsq(const float* __restrict__ x, int N) {
    int w    = (blockIdx.x * blockDim.x + threadIdx.x) >> 5;
    int lane = threadIdx.x & 31;
    if (w >= N) return;
    const float4* xr = reinterpret_cast<const float4*>(x + (size_t)w * D);
    float4 a = xr[lane], b = xr[32 + lane];
    float s = __fadd_rn(
        __fadd_rn(__fadd_rn(__fmul_rn(a.x,a.x), __fmul_rn(a.y,a.y)),
                  __fadd_rn(__fmul_rn(a.z,a.z), __fmul_rn(a.w,a.w))),
        __fadd_rn(__fadd_rn(__fmul_rn(b.x,b.x), __fmul_rn(b.y,b.y)),
                  __fadd_rn(__fmul_rn(b.z,b.z), __fmul_rn(b.w,b.w))));
#pragma unroll
    for (int off = 16; off > 0; off >>= 1) s += __shfl_xor_sync(0xffffffffu, s, off);
    if (lane == 0) g_xsq[w] = s;
}

// ---------------- k_argmin: fused distance GEMM + argmin ----------------
__global__ void __launch_bounds__(256, 2)
k_argmin(const float* __restrict__ x, const float* __restrict__ e, int N, int K) {
    __shared__ ull SM[6144];                 // 48KB exactly
    ull* Xd = SM;                            // 128*32 u64
    ull* Ep = SM + 4096;                     // 64*32 u64
    ull* best = SM + 4096;                   // aliased onto Ep, used only at the end

    int tid = threadIdx.x;
    int tx = tid & 15, ty = tid >> 4;
    int mB = (tx & 7) << 2;
    int m0 = blockIdx.x * TM;

    ull tbest[8];
#pragma unroll
    for (int mi = 0; mi < 8; mi++) tbest[mi] = 0xFFFFFFFFFFFFFFFFULL;

#pragma unroll 1
    for (int kt = 0; kt < K / TN; kt++) {
        int n0 = kt * TN;
        ull acc[8][4];
#pragma unroll
        for (int mi = 0; mi < 8; mi++)
#pragma unroll
            for (int p = 0; p < 4; p++) acc[mi][p] = 0ULL;

#pragma unroll 1
        for (int dc = 0; dc < D / DC; dc++) {
            __syncthreads();
            load_Xdup (Xd, x + (size_t)m0 * D, dc * DC, tid);
            load_Epair(Ep, e + (size_t)n0 * D, dc * DC, tid);
            __syncthreads();
            chunk_mma(Xd, Ep, ty, tx, mB, acc);
        }

        // epilogue: dist = (xsq + esq) - 2*dot
#pragma unroll
        for (int mi = 0; mi < 8; mi++) {
            int m = (mi < 4) ? (4 * ty + mi) : (64 + 4 * ty + (mi - 4));
            float xq = g_xsq[m0 + m];
#pragma unroll
            for (int p = 0; p < 4; p++) {
                float2 v = up2(acc[mi][p]);
                int gk0 = n0 + 32 * p + 2 * tx;
                float d0 = __fsub_rn(__fadd_rn(xq, g_esq[gk0]),     2.0f * v.x);
                float d1 = __fsub_rn(__fadd_rn(xq, g_esq[gk0 + 1]), 2.0f * v.y);
                ull c0 = ((ull)__float_as_uint(d0) << 32) | (unsigned)gk0;
                ull c1 = ((ull)__float_as_uint(d1) << 32) | (unsigned)(gk0 + 1);
                if (c0 < tbest[mi]) tbest[mi] = c0;
                if (c1 < tbest[mi]) tbest[mi] = c1;
            }
        }
    }

    // final cross-thread argmin (best aliases Ep; all compute done)
    __syncthreads();
    if (tid < TM) best[tid] = 0xFFFFFFFFFFFFFFFFULL;
    __syncthreads();
#pragma unroll
    for (int mi = 0; mi < 8; mi++) {
        int m = (mi < 4) ? (4 * ty + mi) : (64 + 4 * ty + (mi - 4));
        atomicMin(&best[m], tbest[mi]);
    }
    __syncthreads();
    if (tid < TM) g_idx[m0 + tid] = (int)(best[tid] & 0xFFFFFFFFu);
}

// ---------------- k_gather ----------------
__global__ void __launch_bounds__(256)
k_gather(const float* __restrict__ x, const float* __restrict__ e,
         float* __restrict__ outq, float* __restrict__ outidx, int N) {
    __shared__ float red[256];
    int tid = threadIdx.x;
    int t   = blockIdx.x * 16 + (tid >> 4);
    int seg = tid & 15;
    int k = g_idx[t];
    const float4* er = reinterpret_cast<const float4*>(e + (size_t)k * D);
    const float4* xr = reinterpret_cast<const float4*>(x + (size_t)t * D);
    float4* qr = reinterpret_cast<float4*>(outq + (size_t)t * D);
    float s = 0.f;
#pragma unroll
    for (int j = 0; j < 4; j++) {
        int c = seg + j * 16;
        float4 q = er[c], xv = xr[c];
        qr[c] = q;
        float dx = q.x - xv.x, dy = q.y - xv.y, dz = q.z - xv.z, dw = q.w - xv.w;
        s += (dx * dx + dy * dy) + (dz * dz + dw * dw);
    }
    red[tid] = s; __syncthreads();
    for (int st = 128; st > 0; st >>= 1) { if (tid < st) red[tid] += red[tid + st]; __syncthreads(); }
    if (tid == 0) atomicAdd(&g_acc[0], red[0]);
    if (seg == 0) {
        outidx[t] = (float)k;
        atomicAdd(&g_counts[k], 1.0f);
    }
}

// ---------------- k_sim: sum |off-diagonal cosine similarity| ----------------
__global__ void __launch_bounds__(256, 2)
k_sim(const float* __restrict__ e, int K) {
    __shared__ ull SM[6144];
    ull* Ad = SM;              // duplicated rows of e (A side)
    ull* Ep = SM + 4096;       // pair-packed rows of e (B side)
    float* red = reinterpret_cast<float*>(SM + 4096);  // aliased, used at end

    int tid = threadIdx.x;
    int tx = tid & 15, ty = tid >> 4;
    int mB = (tx & 7) << 2;
    int m0 = blockIdx.y * TM;
    int n0 = blockIdx.x * TN;

    ull acc[8][4];
#pragma unroll
    for (int mi = 0; mi < 8; mi++)
#pragma unroll
        for (int p = 0; p < 4; p++) acc[mi][p] = 0ULL;

#pragma unroll 1
    for (int dc = 0; dc < D / DC; dc++) {
        __syncthreads();
        load_Xdup (Ad, e + (size_t)m0 * D, dc * DC, tid);
        load_Epair(Ep, e + (size_t)n0 * D, dc * DC, tid);
        __syncthreads();
        chunk_mma(Ad, Ep, ty, tx, mB, acc);
    }

    float s = 0.f;
#pragma unroll
    for (int mi = 0; mi < 8; mi++) {
        int m = (mi < 4) ? (4 * ty + mi) : (64 + 4 * ty + (mi - 4));
        int gm = m0 + m;
        float rim = g_rninv[gm];
#pragma unroll
        for (int p = 0; p < 4; p++) {
            float2 v = up2(acc[mi][p]);
            int gn0 = n0 + 32 * p + 2 * tx;
            float s0 = fabsf(v.x * rim * g_rninv[gn0]);
            float s1 = fabsf(v.y * rim * g_rninv[gn0 + 1]);
            if (gm == gn0)     s0 = 0.f;
            if (gm == gn0 + 1) s1 = 0.f;
            s += s0 + s1;
        }
    }
    __syncthreads();           // all Ep reads done before aliasing as red
    red[tid] = s; __syncthreads();
    for (int st = 128; st > 0; st >>= 1) { if (tid < st) red[tid] += red[tid + st]; __syncthreads(); }
    if (tid == 0) atomicAdd(&g_acc[1], red[0]);
}

// ---------------- k_final ----------------
__global__ void k_final(float* __restrict__ out_loss, float* __restrict__ out_perp, int N, int K) {
    __shared__ float sA[256], sB[256], sC[256];
    int tid = threadIdx.x;

    float tot = 0.f;
    for (int k = tid; k < K; k += 256) tot += g_counts[k];
    sA[tid] = tot; __syncthreads();
    for (int st = 128; st > 0; st >>= 1) { if (tid < st) sA[tid] += sA[tid + st]; __syncthreads(); }
    float total = sA[0];
    __syncthreads();

    float tuni = 1.0f / (float)K;
    float kl = 0.f, pl = 0.f;
    for (int k = tid; k < K; k += 256) {
        float p = g_counts[k] / total;
        kl += (p + EPS_F) * logf((p + EPS_F) / (tuni + EPS_F));
        if (p > 0.f) pl += p * logf(p);
    }
    sB[tid] = kl; sC[tid] = pl; __syncthreads();
    for (int st = 128; st > 0; st >>= 1) {
        if (tid < st) { sB[tid] += sB[tid + st]; sC[tid] += sC[tid + st]; }
        __syncthreads();
    }
    if (tid == 0) {
        float klv = fminf(sB[0], 100.0f);
        float mse = g_acc[0] / ((float)N * (float)D);
        float vq  = mse + COMMIT_COST * mse;
        float l2  = fminf(g_acc[2] / (float)K, 10.0f);
        float orth = fminf(g_acc[1] / ((float)K * (float)K), 10.0f);
        float reg = l2 + orth;
        float loss = fminf(vq + DIV_GAMMA * klv + 0.01f * reg, 100.0f);
        *out_loss = loss;
        *out_perp = expf(-sC[0]);
    }
}

// ---------------- launch ----------------
extern "C" void kernel_launch(void* const* d_in, const int* in_sizes, int n_in,
                              void* d_out, int out_size) {
    const float* x = (const float*)d_in[0];
    const float* e = (const float*)d_in[1];
    float* out = (float*)d_out;

    int N = in_sizes[0] / D;   // 65536
    int K = in_sizes[1] / D;   // 2048
    if (N > MAXN) N = MAXN;
    if (K > MAXK) K = MAXK;

    float* out_q    = out;
    float* out_loss = out + (size_t)N * D;
    float* out_perp = out_loss + 1;
    float* out_idx  = out_perp + 1;

    k_init  <<<(K + 255) / 256, 256>>>(K);
    k_prep  <<<(K + 7) / 8, 256>>>(e, K);
    k_xsq   <<<(N + 7) / 8, 256>>>(x, N);
    k_argmin<<<N / TM, 256>>>(x, e, N, K);
    k_gather<<<N / 16, 256>>>(x, e, out_q, out_idx, N);
    k_sim   <<<dim3(K / TN, K / TM), 256>>>(e, K);
    k_final <<<1, 256>>>(out_loss, out_perp, N, K);
}

// round 3
// speedup vs baseline: 1.8530x; 1.8530x over previous
#include <cuda_runtime.h>

#define D    256
#define DC   32      // d-chunk depth
#define TM   128     // token tile
#define TN   128     // code tile
#define MAXK 2048
#define MAXN 65536

#define COMMIT_COST 0.25f
#define DIV_GAMMA   0.1f
#define EPS_F       1e-8f

typedef unsigned long long ull;

// ---------------- device scratch ----------------
__device__ float g_esq[MAXK];
__device__ float g_rninv[MAXK];
__device__ float g_xsq[MAXN];
__device__ int   g_idx[MAXN];
__device__ float g_counts[MAXK];
__device__ float g_acc[4];   // 0: mse_sum, 1: abs-offdiag sum, 2: rownorm sum

// ---------------- f32x2 packed-FMA helpers ----------------
__device__ __forceinline__ void fma2(ull& c, ull a, ull b) {
    asm("fma.rn.f32x2 %0, %1, %2, %0;" : "+l"(c) : "l"(a), "l"(b));
}
__device__ __forceinline__ float2 up2(ull v) {
    unsigned int lo, hi;
    asm("mov.b64 {%0,%1}, %2;" : "=r"(lo), "=r"(hi) : "l"(v));
    return make_float2(__uint_as_float(lo), __uint_as_float(hi));
}

// ================= tile layouts =================
// Xd: 128 rows x 32 u64. Row m, logical d (0..31): Xd[m][d] = (x[m][d], x[m][d]).
//     Granule g = d/2 (16B). Physical granule = g ^ ((m>>2)&15).
// Ep: 64 pair-rows x 32 u64. Row j, logical d: Ep[j][d] = (e[2j][d], e[2j+1][d]).
//     Physical granule = g ^ (j&15).

__device__ __forceinline__ void load_Xdup(ull* Xd, const float* __restrict__ g,
                                          int d0, int tid) {
    int row  = tid >> 1;
    int half = tid & 1;
    int key  = (row >> 2) & 15;
    const float4* gx = reinterpret_cast<const float4*>(g + (size_t)row * D + d0 + half * 16);
    ull* dst = Xd + row * 32;
#pragma unroll
    for (int i = 0; i < 4; i++) {
        float4 v = gx[i];
        int g0 = half * 8 + i * 2;
        *reinterpret_cast<float4*>(dst + (((g0    ) ^ key) << 1)) = make_float4(v.x, v.x, v.y, v.y);
        *reinterpret_cast<float4*>(dst + (((g0 + 1) ^ key) << 1)) = make_float4(v.z, v.z, v.w, v.w);
    }
}

__device__ __forceinline__ void load_Epair(ull* Ep, const float* __restrict__ g,
                                           int d0, int tid) {
    int j = tid >> 2;
    int q = tid & 3;
    int key = j & 15;
    const float* e0 = g + (size_t)(2 * j) * D + d0;
    const float* e1 = e0 + D;
    ull* base = Ep + j * 32;
#pragma unroll
    for (int gidx = 0; gidx < 2; gidx++) {
        int dq = (q + 4 * gidx) * 4;              // starting d: 0..28 step 4
        int g0 = dq >> 1;                         // starting granule (even)
        float4 a = *reinterpret_cast<const float4*>(e0 + dq);
        float4 b = *reinterpret_cast<const float4*>(e1 + dq);
        *reinterpret_cast<float4*>(base + (((g0    ) ^ key) << 1)) = make_float4(a.x, b.x, a.y, b.y);
        *reinterpret_cast<float4*>(base + (((g0 + 1) ^ key) << 1)) = make_float4(a.z, b.z, a.w, b.w);
    }
}

// ================= 128x128x32 chunk MMA =================
// acc[mi][pg]: mi -> token rows {4ty+0..3, 64+4ty+0..3}
//              pg -> code pair (n0 + 32*pg + 2*tx, +1)
__device__ __forceinline__ void chunk_mma(const ull* __restrict__ Xd,
                                          const ull* __restrict__ Ep,
                                          int ty, int tx,
                                          ull acc[8][4]) {
    const ull* __restrict__ Xt = Xd + (size_t)ty * 128;   // ty*4 rows * 32 u64
    const ull* __restrict__ Et = Ep + (size_t)tx * 32;    // row tx base
#pragma unroll
    for (int hs = 0; hs < 16; hs++) {             // 2 d-values per half-step
        const ull* pB = Et + (((hs ^ tx) & 15) << 1);
        const ull* pA = Xt + (((hs ^ ty) & 15) << 1);
        ulonglong2 b2[4];
        b2[0] = *reinterpret_cast<const ulonglong2*>(pB);
        b2[1] = *reinterpret_cast<const ulonglong2*>(pB + 16 * 32);
        b2[2] = *reinterpret_cast<const ulonglong2*>(pB + 32 * 32);
        b2[3] = *reinterpret_cast<const ulonglong2*>(pB + 48 * 32);
#pragma unroll
        for (int mi = 0; mi < 8; mi++) {
            int moff = (mi < 4) ? (mi * 32) : ((64 - 4) * 32 + mi * 32);  // (m - 4ty)*32
            ulonglong2 a2 = *reinterpret_cast<const ulonglong2*>(pA + moff);
            fma2(acc[mi][0], a2.x, b2[0].x);
            fma2(acc[mi][1], a2.x, b2[1].x);
            fma2(acc[mi][2], a2.x, b2[2].x);
            fma2(acc[mi][3], a2.x, b2[3].x);
            fma2(acc[mi][0], a2.y, b2[0].y);
            fma2(acc[mi][1], a2.y, b2[1].y);
            fma2(acc[mi][2], a2.y, b2[2].y);
            fma2(acc[mi][3], a2.y, b2[3].y);
        }
    }
}

// ---------------- k_init ----------------
__global__ void k_init(int K) {
    int i = blockIdx.x * blockDim.x + threadIdx.x;
    if (i < K) g_counts[i] = 0.f;
    if (i < 4) g_acc[i] = 0.f;
}

// ---------------- k_prep: esq, 1/rownorm, sum(rownorm) ----------------
__global__ void k_prep(const float* __restrict__ e, int K) {
    int w    = (blockIdx.x * blockDim.x + threadIdx.x) >> 5;
    int lane = threadIdx.x & 31;
    if (w >= K) return;
    const float4* er = reinterpret_cast<const float4*>(e + (size_t)w * D);
    float4 a = er[lane], b = er[32 + lane];
    float s = __fadd_rn(
        __fadd_rn(__fadd_rn(__fmul_rn(a.x,a.x), __fmul_rn(a.y,a.y)),
                  __fadd_rn(__fmul_rn(a.z,a.z), __fmul_rn(a.w,a.w))),
        __fadd_rn(__fadd_rn(__fmul_rn(b.x,b.x), __fmul_rn(b.y,b.y)),
                  __fadd_rn(__fmul_rn(b.z,b.z), __fmul_rn(b.w,b.w))));
#pragma unroll
    for (int off = 16; off > 0; off >>= 1) s += __shfl_xor_sync(0xffffffffu, s, off);
    if (lane == 0) {
        g_esq[w] = s;
        float rn = sqrtf(s);
        g_rninv[w] = 1.0f / fmaxf(rn, 1e-12f);
        atomicAdd(&g_acc[2], rn);
    }
}

// ---------------- k_xsq ----------------
__global__ void k_xsq(const float* __restrict__ x, int N) {
    int w    = (blockIdx.x * blockDim.x + threadIdx.x) >> 5;
    int lane = threadIdx.x & 31;
    if (w >= N) return;
    const float4* xr = reinterpret_cast<const float4*>(x + (size_t)w * D);
    float4 a = xr[lane], b = xr[32 + lane];
    float s = __fadd_rn(
        __fadd_rn(__fadd_rn(__fmul_rn(a.x,a.x), __fmul_rn(a.y,a.y)),
                  __fadd_rn(__fmul_rn(a.z,a.z), __fmul_rn(a.w,a.w))),
        __fadd_rn(__fadd_rn(__fmul_rn(b.x,b.x), __fmul_rn(b.y,b.y)),
                  __fadd_rn(__fmul_rn(b.z,b.z), __fmul_rn(b.w,b.w))));
#pragma unroll
    for (int off = 16; off > 0; off >>= 1) s += __shfl_xor_sync(0xffffffffu, s, off);
    if (lane == 0) g_xsq[w] = s;
}

// ---------------- k_argmin: fused distance GEMM + argmin ----------------
__global__ void __launch_bounds__(256, 2)
k_argmin(const float* __restrict__ x, const float* __restrict__ e, int N, int K) {
    __shared__ ull SM[6144];                 // 48KB exactly
    ull* Xd = SM;                            // 128*32 u64
    ull* Ep = SM + 4096;                     // 64*32 u64
    ull* best = SM + 4096;                   // aliased onto Ep, used only at the end

    int tid = threadIdx.x;
    int tx = tid & 15, ty = tid >> 4;
    int m0 = blockIdx.x * TM;

    ull tbest[8];
#pragma unroll
    for (int mi = 0; mi < 8; mi++) tbest[mi] = 0xFFFFFFFFFFFFFFFFULL;

#pragma unroll 1
    for (int kt = 0; kt < K / TN; kt++) {
        int n0 = kt * TN;
        ull acc[8][4];
#pragma unroll
        for (int mi = 0; mi < 8; mi++)
#pragma unroll
            for (int p = 0; p < 4; p++) acc[mi][p] = 0ULL;

#pragma unroll 1
        for (int dc = 0; dc < D / DC; dc++) {
            __syncthreads();
            load_Xdup (Xd, x + (size_t)m0 * D, dc * DC, tid);
            load_Epair(Ep, e + (size_t)n0 * D, dc * DC, tid);
            __syncthreads();
            chunk_mma(Xd, Ep, ty, tx, acc);
        }

        // epilogue: dist = (xsq + esq) - 2*dot
#pragma unroll
        for (int mi = 0; mi < 8; mi++) {
            int m = (mi < 4) ? (4 * ty + mi) : (64 + 4 * ty + (mi - 4));
            float xq = g_xsq[m0 + m];
#pragma unroll
            for (int p = 0; p < 4; p++) {
                float2 v = up2(acc[mi][p]);
                int gk0 = n0 + 32 * p + 2 * tx;
                float d0 = __fsub_rn(__fadd_rn(xq, g_esq[gk0]),     2.0f * v.x);
                float d1 = __fsub_rn(__fadd_rn(xq, g_esq[gk0 + 1]), 2.0f * v.y);
                ull c0 = ((ull)__float_as_uint(d0) << 32) | (unsigned)gk0;
                ull c1 = ((ull)__float_as_uint(d1) << 32) | (unsigned)(gk0 + 1);
                if (c0 < tbest[mi]) tbest[mi] = c0;
                if (c1 < tbest[mi]) tbest[mi] = c1;
            }
        }
    }

    // final cross-thread argmin (best aliases Ep; all compute done)
    __syncthreads();
    if (tid < TM) best[tid] = 0xFFFFFFFFFFFFFFFFULL;
    __syncthreads();
#pragma unroll
    for (int mi = 0; mi < 8; mi++) {
        int m = (mi < 4) ? (4 * ty + mi) : (64 + 4 * ty + (mi - 4));
        atomicMin(&best[m], tbest[mi]);
    }
    __syncthreads();
    if (tid < TM) g_idx[m0 + tid] = (int)(best[tid] & 0xFFFFFFFFu);
}

// ---------------- k_gather ----------------
__global__ void __launch_bounds__(256)
k_gather(const float* __restrict__ x, const float* __restrict__ e,
         float* __restrict__ outq, float* __restrict__ outidx, int N) {
    __shared__ float red[256];
    int tid = threadIdx.x;
    int t   = blockIdx.x * 16 + (tid >> 4);
    int seg = tid & 15;
    int k = g_idx[t];
    const float4* er = reinterpret_cast<const float4*>(e + (size_t)k * D);
    const float4* xr = reinterpret_cast<const float4*>(x + (size_t)t * D);
    float4* qr = reinterpret_cast<float4*>(outq + (size_t)t * D);
    float s = 0.f;
#pragma unroll
    for (int j = 0; j < 4; j++) {
        int c = seg + j * 16;
        float4 q = er[c], xv = xr[c];
        qr[c] = q;
        float dx = q.x - xv.x, dy = q.y - xv.y, dz = q.z - xv.z, dw = q.w - xv.w;
        s += (dx * dx + dy * dy) + (dz * dz + dw * dw);
    }
    red[tid] = s; __syncthreads();
    for (int st = 128; st > 0; st >>= 1) { if (tid < st) red[tid] += red[tid + st]; __syncthreads(); }
    if (tid == 0) atomicAdd(&g_acc[0], red[0]);
    if (seg == 0) {
        outidx[t] = (float)k;
        atomicAdd(&g_counts[k], 1.0f);
    }
}

// ---------------- k_sim: sum |off-diagonal cosine similarity| ----------------
__global__ void __launch_bounds__(256, 2)
k_sim(const float* __restrict__ e, int K) {
    __shared__ ull SM[6144];
    ull* Ad = SM;              // duplicated rows of e (A side)
    ull* Ep = SM + 4096;       // pair-packed rows of e (B side)
    float* red = reinterpret_cast<float*>(SM + 4096);  // aliased, used at end

    int tid = threadIdx.x;
    int tx = tid & 15, ty = tid >> 4;
    int m0 = blockIdx.y * TM;
    int n0 = blockIdx.x * TN;

    ull acc[8][4];
#pragma unroll
    for (int mi = 0; mi < 8; mi++)
#pragma unroll
        for (int p = 0; p < 4; p++) acc[mi][p] = 0ULL;

#pragma unroll 1
    for (int dc = 0; dc < D / DC; dc++) {
        __syncthreads();
        load_Xdup (Ad, e + (size_t)m0 * D, dc * DC, tid);
        load_Epair(Ep, e + (size_t)n0 * D, dc * DC, tid);
        __syncthreads();
        chunk_mma(Ad, Ep, ty, tx, acc);
    }

    float s = 0.f;
#pragma unroll
    for (int mi = 0; mi < 8; mi++) {
        int m = (mi < 4) ? (4 * ty + mi) : (64 + 4 * ty + (mi - 4));
        int gm = m0 + m;
        float rim = g_rninv[gm];
#pragma unroll
        for (int p = 0; p < 4; p++) {
            float2 v = up2(acc[mi][p]);
            int gn0 = n0 + 32 * p + 2 * tx;
            float s0 = fabsf(v.x * rim * g_rninv[gn0]);
            float s1 = fabsf(v.y * rim * g_rninv[gn0 + 1]);
            if (gm == gn0)     s0 = 0.f;
            if (gm == gn0 + 1) s1 = 0.f;
            s += s0 + s1;
        }
    }
    __syncthreads();           // all Ep reads done before aliasing as red
    red[tid] = s; __syncthreads();
    for (int st = 128; st > 0; st >>= 1) { if (tid < st) red[tid] += red[tid + st]; __syncthreads(); }
    if (tid == 0) atomicAdd(&g_acc[1], red[0]);
}

// ---------------- k_final ----------------
__global__ void k_final(float* __restrict__ out_loss, float* __restrict__ out_perp, int N, int K) {
    __shared__ float sA[256], sB[256], sC[256];
    int tid = threadIdx.x;

    float tot = 0.f;
    for (int k = tid; k < K; k += 256) tot += g_counts[k];
    sA[tid] = tot; __syncthreads();
    for (int st = 128; st > 0; st >>= 1) { if (tid < st) sA[tid] += sA[tid + st]; __syncthreads(); }
    float total = sA[0];
    __syncthreads();

    float tuni = 1.0f / (float)K;
    float kl = 0.f, pl = 0.f;
    for (int k = tid; k < K; k += 256) {
        float p = g_counts[k] / total;
        kl += (p + EPS_F) * logf((p + EPS_F) / (tuni + EPS_F));
        if (p > 0.f) pl += p * logf(p);
    }
    sB[tid] = kl; sC[tid] = pl; __syncthreads();
    for (int st = 128; st > 0; st >>= 1) {
        if (tid < st) { sB[tid] += sB[tid + st]; sC[tid] += sC[tid + st]; }
        __syncthreads();
    }
    if (tid == 0) {
        float klv = fminf(sB[0], 100.0f);
        float mse = g_acc[0] / ((float)N * (float)D);
        float vq  = mse + COMMIT_COST * mse;
        float l2  = fminf(g_acc[2] / (float)K, 10.0f);
        float orth = fminf(g_acc[1] / ((float)K * (float)K), 10.0f);
        float reg = l2 + orth;
        float loss = fminf(vq + DIV_GAMMA * klv + 0.01f * reg, 100.0f);
        *out_loss = loss;
        *out_perp = expf(-sC[0]);
    }
}

// ---------------- launch ----------------
extern "C" void kernel_launch(void* const* d_in, const int* in_sizes, int n_in,
                              void* d_out, int out_size) {
    const float* x = (const float*)d_in[0];
    const float* e = (const float*)d_in[1];
    float* out = (float*)d_out;

    int N = in_sizes[0] / D;   // 65536
    int K = in_sizes[1] / D;   // 2048
    if (N > MAXN) N = MAXN;
    if (K > MAXK) K = MAXK;

    float* out_q    = out;
    float* out_loss = out + (size_t)N * D;
    float* out_perp = out_loss + 1;
    float* out_idx  = out_perp + 1;

    k_init  <<<(K + 255) / 256, 256>>>(K);
    k_prep  <<<(K + 7) / 8, 256>>>(e, K);
    k_xsq   <<<(N + 7) / 8, 256>>>(x, N);
    k_argmin<<<N / TM, 256>>>(x, e, N, K);
    k_gather<<<N / 16, 256>>>(x, e, out_q, out_idx, N);
    k_sim   <<<dim3(K / TN, K / TM), 256>>>(e, K);
    k_final <<<1, 256>>>(out_loss, out_perp, N, K);
}

// round 5
// speedup vs baseline: 2.3834x; 1.2862x over previous
#include <cuda_runtime.h>
#include <cstdint>

#define D    256
#define TM   128
#define TN   128
#define MAXK 2048
#define MAXN 65536

#define COMMIT_COST 0.25f
#define DIV_GAMMA   0.1f
#define EPS_F       1e-8f

typedef unsigned long long ull;

// ---------------- device scratch ----------------
__device__ float g_esq[MAXK];
__device__ float g_rninv[MAXK];
__device__ float g_xsq[MAXN];
__device__ int   g_idx[MAXN];
__device__ float g_counts[MAXK];
__device__ float g_acc[4];

// tf32 hi/lo splits
__device__ float4 g_xhi[MAXN * D / 4];
__device__ float4 g_xlo[MAXN * D / 4];
__device__ float4 g_ehi[MAXK * D / 4];
__device__ float4 g_elo[MAXK * D / 4];

// ---------------- helpers ----------------
__device__ __forceinline__ uint32_t smem_u32(const void* p) {
    uint32_t a;
    asm("{ .reg .u64 t; cvta.to.shared.u64 t, %1; cvt.u32.u64 %0, t; }" : "=r"(a) : "l"(p));
    return a;
}
__device__ __forceinline__ float tf32r(float v) {
    uint32_t u;
    asm("cvt.rna.tf32.f32 %0, %1;" : "=r"(u) : "f"(v));
    return __uint_as_float(u);
}
__device__ __forceinline__ void fma2(ull& c, ull a, ull b) {
    asm("fma.rn.f32x2 %0, %1, %2, %0;" : "+l"(c) : "l"(a), "l"(b));
}
__device__ __forceinline__ float2 up2(ull v) {
    unsigned int lo, hi;
    asm("mov.b64 {%0,%1}, %2;" : "=r"(lo), "=r"(hi) : "l"(v));
    return make_float2(__uint_as_float(lo), __uint_as_float(hi));
}
__device__ __forceinline__ void ldsm_x4(uint32_t& d0, uint32_t& d1, uint32_t& d2, uint32_t& d3,
                                        uint32_t addr) {
    asm volatile("ldmatrix.sync.aligned.m8n8.x4.shared.b16 {%0,%1,%2,%3}, [%4];"
        : "=r"(d0), "=r"(d1), "=r"(d2), "=r"(d3) : "r"(addr));
}
__device__ __forceinline__ void mma_tf32(float* c, const uint32_t* a, const uint32_t* b) {
    asm volatile(
        "mma.sync.aligned.m16n8k8.row.col.f32.tf32.tf32.f32 "
        "{%0,%1,%2,%3}, {%4,%5,%6,%7}, {%8,%9}, {%0,%1,%2,%3};"
        : "+f"(c[0]), "+f"(c[1]), "+f"(c[2]), "+f"(c[3])
        : "r"(a[0]), "r"(a[1]), "r"(a[2]), "r"(a[3]), "r"(b[0]), "r"(b[1]));
}

// ---------------- k_init ----------------
__global__ void k_init(int K) {
    int i = blockIdx.x * blockDim.x + threadIdx.x;
    if (i < K) g_counts[i] = 0.f;
    if (i < 4) g_acc[i] = 0.f;
}

// ---------------- k_prep ----------------
__global__ void k_prep(const float* __restrict__ e, int K) {
    int w    = (blockIdx.x * blockDim.x + threadIdx.x) >> 5;
    int lane = threadIdx.x & 31;
    if (w >= K) return;
    const float4* er = reinterpret_cast<const float4*>(e + (size_t)w * D);
    float4 a = er[lane], b = er[32 + lane];
    float s = __fadd_rn(
        __fadd_rn(__fadd_rn(__fmul_rn(a.x,a.x), __fmul_rn(a.y,a.y)),
                  __fadd_rn(__fmul_rn(a.z,a.z), __fmul_rn(a.w,a.w))),
        __fadd_rn(__fadd_rn(__fmul_rn(b.x,b.x), __fmul_rn(b.y,b.y)),
                  __fadd_rn(__fmul_rn(b.z,b.z), __fmul_rn(b.w,b.w))));
#pragma unroll
    for (int off = 16; off > 0; off >>= 1) s += __shfl_xor_sync(0xffffffffu, s, off);
    if (lane == 0) {
        g_esq[w] = s;
        float rn = sqrtf(s);
        g_rninv[w] = 1.0f / fmaxf(rn, 1e-12f);
        atomicAdd(&g_acc[2], rn);
    }
}

// ---------------- k_xsq ----------------
__global__ void k_xsq(const float* __restrict__ x, int N) {
    int w    = (blockIdx.x * blockDim.x + threadIdx.x) >> 5;
    int lane = threadIdx.x & 31;
    if (w >= N) return;
    const float4* xr = reinterpret_cast<const float4*>(x + (size_t)w * D);
    float4 a = xr[lane], b = xr[32 + lane];
    float s = __fadd_rn(
        __fadd_rn(__fadd_rn(__fmul_rn(a.x,a.x), __fmul_rn(a.y,a.y)),
                  __fadd_rn(__fmul_rn(a.z,a.z), __fmul_rn(a.w,a.w))),
        __fadd_rn(__fadd_rn(__fmul_rn(b.x,b.x), __fmul_rn(b.y,b.y)),
                  __fadd_rn(__fmul_rn(b.z,b.z), __fmul_rn(b.w,b.w))));
#pragma unroll
    for (int off = 16; off > 0; off >>= 1) s += __shfl_xor_sync(0xffffffffu, s, off);
    if (lane == 0) g_xsq[w] = s;
}

// ---------------- k_split: tf32 hi/lo ----------------
__device__ __forceinline__ void split4(float4 v, float4& h, float4& l) {
    h.x = tf32r(v.x); l.x = tf32r(v.x - h.x);
    h.y = tf32r(v.y); l.y = tf32r(v.y - h.y);
    h.z = tf32r(v.z); l.z = tf32r(v.z - h.z);
    h.w = tf32r(v.w); l.w = tf32r(v.w - h.w);
}
__global__ void k_split_x(const float4* __restrict__ src, int n4) {
    int i = blockIdx.x * blockDim.x + threadIdx.x;
    if (i >= n4) return;
    float4 h, l; split4(src[i], h, l);
    g_xhi[i] = h; g_xlo[i] = l;
}
__global__ void k_split_e(const float4* __restrict__ src, int n4) {
    int i = blockIdx.x * blockDim.x + threadIdx.x;
    if (i >= n4) return;
    float4 h, l; split4(src[i], h, l);
    g_ehi[i] = h; g_elo[i] = l;
}

// ---------------- k_argmin_mma: tf32x3 mma.sync distance GEMM + fused argmin ----------------
// smem: Ahi[128x32f] | Alo | Bhi | Blo  (16KB each, XOR-swizzled 16B granules), best[128] u64
#define A_HI 0
#define A_LO 16384
#define B_HI 32768
#define B_LO 49152
#define OFF_BEST 65536
#define SMEM_MMA (65536 + 1024)

// coalesced chunk loader: 128 rows x 32 floats (8 granules), phys granule = g ^ (row&7)
__device__ __forceinline__ void load_chunk(char* dst, const float4* __restrict__ src,
                                           int base_f4, int tid) {
#pragma unroll
    for (int rep = 0; rep < 4; rep++) {
        int id  = tid + rep * 256;
        int row = id >> 3;
        int g   = id & 7;
        int phys = g ^ (row & 7);
        *reinterpret_cast<float4*>(dst + row * 128 + phys * 16) = src[base_f4 + row * 64 + g];
    }
}

__global__ void __launch_bounds__(256, 2)
k_argmin_mma(int N, int K) {
    extern __shared__ char dsm[];
    uint32_t smb = smem_u32(dsm);
    int tid  = threadIdx.x;
    int lane = tid & 31;
    int wid  = tid >> 5;
    int wm   = wid >> 2;      // 0..1 : m-offset 64*wm
    int wn   = wid & 3;       // 0..3 : n-offset 32*wn
    int m0   = blockIdx.x * 128;

    // ldmatrix lane-address precompute
    int asub = lane >> 4;                 // granule +0/+1
    int bsub = (lane >> 3) & 1;
    int aoff[4], akey[4];
#pragma unroll
    for (int ma = 0; ma < 4; ma++) {
        int row = wm * 64 + ma * 16 + ((lane >> 3) & 1) * 8 + (lane & 7);
        aoff[ma] = row * 128;
        akey[ma] = row & 7;
    }
    int boff[2], bkey[2];
#pragma unroll
    for (int nb = 0; nb < 2; nb++) {
        int row = wn * 32 + nb * 16 + ((lane >> 4) & 1) * 8 + (lane & 7);
        boff[nb] = row * 128;
        bkey[nb] = row & 7;
    }

    ull tbest[8];
#pragma unroll
    for (int i = 0; i < 8; i++) tbest[i] = 0xFFFFFFFFFFFFFFFFULL;

    int NT = K / 128;
#pragma unroll 1
    for (int nt = 0; nt < NT; nt++) {
        float acc[4][4][4];
#pragma unroll
        for (int ma = 0; ma < 4; ma++)
#pragma unroll
            for (int na = 0; na < 4; na++)
#pragma unroll
                for (int c = 0; c < 4; c++) acc[ma][na][c] = 0.f;

#pragma unroll 1
        for (int dc = 0; dc < 8; dc++) {
            __syncthreads();
            int abase_f4 = m0 * 64 + dc * 8;
            int bbase_f4 = nt * 128 * 64 + dc * 8;
            load_chunk(dsm + A_HI, g_xhi, abase_f4, tid);
            load_chunk(dsm + A_LO, g_xlo, abase_f4, tid);
            load_chunk(dsm + B_HI, g_ehi, bbase_f4, tid);
            load_chunk(dsm + B_LO, g_elo, bbase_f4, tid);
            __syncthreads();

#pragma unroll
            for (int pass = 0; pass < 3; pass++) {
                uint32_t ab = smb + ((pass == 2) ? A_LO : A_HI);
                uint32_t bb = smb + ((pass == 1) ? B_LO : B_HI);
#pragma unroll
                for (int ks = 0; ks < 4; ks++) {
                    int ga = ks * 2 + asub;
                    int gb = ks * 2 + bsub;
                    uint32_t ar[4][4], br[4][2];
#pragma unroll
                    for (int ma = 0; ma < 4; ma++)
                        ldsm_x4(ar[ma][0], ar[ma][1], ar[ma][2], ar[ma][3],
                                ab + aoff[ma] + (((ga ^ akey[ma]) & 7) << 4));
#pragma unroll
                    for (int nb = 0; nb < 2; nb++) {
                        uint32_t d0, d1, d2, d3;
                        ldsm_x4(d0, d1, d2, d3,
                                bb + boff[nb] + (((gb ^ bkey[nb]) & 7) << 4));
                        br[2 * nb][0] = d0; br[2 * nb][1] = d1;
                        br[2 * nb + 1][0] = d2; br[2 * nb + 1][1] = d3;
                    }
#pragma unroll
                    for (int ma = 0; ma < 4; ma++)
#pragma unroll
                        for (int na = 0; na < 4; na++)
                            mma_tf32(acc[ma][na], ar[ma], br[na]);
                }
            }
        }

        // epilogue: dist = (xsq + esq) - 2*dot, fused packed argmin
#pragma unroll
        for (int ma = 0; ma < 4; ma++) {
            int m_r = m0 + wm * 64 + ma * 16 + (lane >> 2);
            float xq0 = g_xsq[m_r];
            float xq1 = g_xsq[m_r + 8];
#pragma unroll
            for (int na = 0; na < 4; na++) {
                int n0c = nt * 128 + wn * 32 + na * 8 + 2 * (lane & 3);
                float e0 = g_esq[n0c], e1 = g_esq[n0c + 1];
                float d00 = __fsub_rn(__fadd_rn(xq0, e0), 2.0f * acc[ma][na][0]);
                float d01 = __fsub_rn(__fadd_rn(xq0, e1), 2.0f * acc[ma][na][1]);
                float d10 = __fsub_rn(__fadd_rn(xq1, e0), 2.0f * acc[ma][na][2]);
                float d11 = __fsub_rn(__fadd_rn(xq1, e1), 2.0f * acc[ma][na][3]);
                ull c00 = ((ull)__float_as_uint(d00) << 32) | (unsigned)n0c;
                ull c01 = ((ull)__float_as_uint(d01) << 32) | (unsigned)(n0c + 1);
                ull c10 = ((ull)__float_as_uint(d10) << 32) | (unsigned)n0c;
                ull c11 = ((ull)__float_as_uint(d11) << 32) | (unsigned)(n0c + 1);
                if (c00 < tbest[ma * 2])     tbest[ma * 2] = c00;
                if (c01 < tbest[ma * 2])     tbest[ma * 2] = c01;
                if (c10 < tbest[ma * 2 + 1]) tbest[ma * 2 + 1] = c10;
                if (c11 < tbest[ma * 2 + 1]) tbest[ma * 2 + 1] = c11;
            }
        }
    }

    // cross-thread argmin
    ull* best = reinterpret_cast<ull*>(dsm + OFF_BEST);
    __syncthreads();
    if (tid < 128) best[tid] = 0xFFFFFFFFFFFFFFFFULL;
    __syncthreads();
#pragma unroll
    for (int ma = 0; ma < 4; ma++) {
        int mloc = wm * 64 + ma * 16 + (lane >> 2);
        atomicMin(&best[mloc],     tbest[ma * 2]);
        atomicMin(&best[mloc + 8], tbest[ma * 2 + 1]);
    }
    __syncthreads();
    if (tid < 128) g_idx[m0 + tid] = (int)(best[tid] & 0xFFFFFFFFu);
}

// ---------------- k_gather ----------------
__global__ void __launch_bounds__(256)
k_gather(const float* __restrict__ x, const float* __restrict__ e,
         float* __restrict__ outq, float* __restrict__ outidx, int N) {
    __shared__ float red[256];
    int tid = threadIdx.x;
    int t   = blockIdx.x * 16 + (tid >> 4);
    int seg = tid & 15;
    int k = g_idx[t];
    const float4* er = reinterpret_cast<const float4*>(e + (size_t)k * D);
    const float4* xr = reinterpret_cast<const float4*>(x + (size_t)t * D);
    float4* qr = reinterpret_cast<float4*>(outq + (size_t)t * D);
    float s = 0.f;
#pragma unroll
    for (int j = 0; j < 4; j++) {
        int c = seg + j * 16;
        float4 q = er[c], xv = xr[c];
        qr[c] = q;
        float dx = q.x - xv.x, dy = q.y - xv.y, dz = q.z - xv.z, dw = q.w - xv.w;
        s += (dx * dx + dy * dy) + (dz * dz + dw * dw);
    }
    red[tid] = s; __syncthreads();
    for (int st = 128; st > 0; st >>= 1) { if (tid < st) red[tid] += red[tid + st]; __syncthreads(); }
    if (tid == 0) atomicAdd(&g_acc[0], red[0]);
    if (seg == 0) {
        outidx[t] = (float)k;
        atomicAdd(&g_counts[k], 1.0f);
    }
}

// ================= FFMA2 machinery for k_sim =================
__device__ __forceinline__ void load_Xdup(ull* Xd, const float* __restrict__ g,
                                          int d0, int tid) {
    int row  = tid >> 1;
    int half = tid & 1;
    int key  = (row >> 2) & 15;
    const float4* gx = reinterpret_cast<const float4*>(g + (size_t)row * D + d0 + half * 16);
    ull* dst = Xd + row * 32;
#pragma unroll
    for (int i = 0; i < 4; i++) {
        float4 v = gx[i];
        int g0 = half * 8 + i * 2;
        *reinterpret_cast<float4*>(dst + (((g0    ) ^ key) << 1)) = make_float4(v.x, v.x, v.y, v.y);
        *reinterpret_cast<float4*>(dst + (((g0 + 1) ^ key) << 1)) = make_float4(v.z, v.z, v.w, v.w);
    }
}
__device__ __forceinline__ void load_Epair(ull* Ep, const float* __restrict__ g,
                                           int d0, int tid) {
    int j = tid >> 2;
    int q = tid & 3;
    int key = j & 15;
    const float* e0 = g + (size_t)(2 * j) * D + d0;
    const float* e1 = e0 + D;
    ull* base = Ep + j * 32;
#pragma unroll
    for (int gidx = 0; gidx < 2; gidx++) {
        int dq = (q + 4 * gidx) * 4;
        int g0 = dq >> 1;
        float4 a = *reinterpret_cast<const float4*>(e0 + dq);
        float4 b = *reinterpret_cast<const float4*>(e1 + dq);
        *reinterpret_cast<float4*>(base + (((g0    ) ^ key) << 1)) = make_float4(a.x, b.x, a.y, b.y);
        *reinterpret_cast<float4*>(base + (((g0 + 1) ^ key) << 1)) = make_float4(a.z, b.z, a.w, b.w);
    }
}
__device__ __forceinline__ void chunk_mma_f(const ull* __restrict__ Xd,
                                            const ull* __restrict__ Ep,
                                            int ty, int tx,
                                            ull acc[8][4]) {
    const ull* __restrict__ Xt = Xd + (size_t)ty * 128;
    const ull* __restrict__ Et = Ep + (size_t)tx * 32;
#pragma unroll
    for (int hs = 0; hs < 16; hs++) {
        const ull* pB = Et + (((hs ^ tx) & 15) << 1);
        const ull* pA = Xt + (((hs ^ ty) & 15) << 1);
        ulonglong2 b2[4];
        b2[0] = *reinterpret_cast<const ulonglong2*>(pB);
        b2[1] = *reinterpret_cast<const ulonglong2*>(pB + 16 * 32);
        b2[2] = *reinterpret_cast<const ulonglong2*>(pB + 32 * 32);
        b2[3] = *reinterpret_cast<const ulonglong2*>(pB + 48 * 32);
#pragma unroll
        for (int mi = 0; mi < 8; mi++) {
            int moff = (mi < 4) ? (mi * 32) : ((64 - 4) * 32 + mi * 32);
            ulonglong2 a2 = *reinterpret_cast<const ulonglong2*>(pA + moff);
            fma2(acc[mi][0], a2.x, b2[0].x);
            fma2(acc[mi][1], a2.x, b2[1].x);
            fma2(acc[mi][2], a2.x, b2[2].x);
            fma2(acc[mi][3], a2.x, b2[3].x);
            fma2(acc[mi][0], a2.y, b2[0].y);
            fma2(acc[mi][1], a2.y, b2[1].y);
            fma2(acc[mi][2], a2.y, b2[2].y);
            fma2(acc[mi][3], a2.y, b2[3].y);
        }
    }
}

// ---------------- k_sim ----------------
__global__ void __launch_bounds__(256, 2)
k_sim(const float* __restrict__ e, int K) {
    __shared__ ull SM[6144];
    ull* Ad = SM;
    ull* Ep = SM + 4096;
    float* red = reinterpret_cast<float*>(SM + 4096);

    int tid = threadIdx.x;
    int tx = tid & 15, ty = tid >> 4;
    int m0 = blockIdx.y * TM;
    int n0 = blockIdx.x * TN;

    ull acc[8][4];
#pragma unroll
    for (int mi = 0; mi < 8; mi++)
#pragma unroll
        for (int p = 0; p < 4; p++) acc[mi][p] = 0ULL;

#pragma unroll 1
    for (int dc = 0; dc < 8; dc++) {
        __syncthreads();
        load_Xdup (Ad, e + (size_t)m0 * D, dc * 32, tid);
        load_Epair(Ep, e + (size_t)n0 * D, dc * 32, tid);
        __syncthreads();
        chunk_mma_f(Ad, Ep, ty, tx, acc);
    }

    float s = 0.f;
#pragma unroll
    for (int mi = 0; mi < 8; mi++) {
        int m = (mi < 4) ? (4 * ty + mi) : (64 + 4 * ty + (mi - 4));
        int gm = m0 + m;
        float rim = g_rninv[gm];
#pragma unroll
        for (int p = 0; p < 4; p++) {
            float2 v = up2(acc[mi][p]);
            int gn0 = n0 + 32 * p + 2 * tx;
            float s0 = fabsf(v.x * rim * g_rninv[gn0]);
            float s1 = fabsf(v.y * rim * g_rninv[gn0 + 1]);
            if (gm == gn0)     s0 = 0.f;
            if (gm == gn0 + 1) s1 = 0.f;
            s += s0 + s1;
        }
    }
    __syncthreads();
    red[tid] = s; __syncthreads();
    for (int st = 128; st > 0; st >>= 1) { if (tid < st) red[tid] += red[tid + st]; __syncthreads(); }
    if (tid == 0) atomicAdd(&g_acc[1], red[0]);
}

// ---------------- k_final ----------------
__global__ void k_final(float* __restrict__ out_loss, float* __restrict__ out_perp, int N, int K) {
    __shared__ float sA[256], sB[256], sC[256];
    int tid = threadIdx.x;

    float tot = 0.f;
    for (int k = tid; k < K; k += 256) tot += g_counts[k];
    sA[tid] = tot; __syncthreads();
    for (int st = 128; st > 0; st >>= 1) { if (tid < st) sA[tid] += sA[tid + st]; __syncthreads(); }
    float total = sA[0];
    __syncthreads();

    float tuni = 1.0f / (float)K;
    float kl = 0.f, pl = 0.f;
    for (int k = tid; k < K; k += 256) {
        float p = g_counts[k] / total;
        kl += (p + EPS_F) * logf((p + EPS_F) / (tuni + EPS_F));
        if (p > 0.f) pl += p * logf(p);
    }
    sB[tid] = kl; sC[tid] = pl; __syncthreads();
    for (int st = 128; st > 0; st >>= 1) {
        if (tid < st) { sB[tid] += sB[tid + st]; sC[tid] += sC[tid + st]; }
        __syncthreads();
    }
    if (tid == 0) {
        float klv = fminf(sB[0], 100.0f);
        float mse = g_acc[0] / ((float)N * (float)D);
        float vq  = mse + COMMIT_COST * mse;
        float l2  = fminf(g_acc[2] / (float)K, 10.0f);
        float orth = fminf(g_acc[1] / ((float)K * (float)K), 10.0f);
        float reg = l2 + orth;
        float loss = fminf(vq + DIV_GAMMA * klv + 0.01f * reg, 100.0f);
        *out_loss = loss;
        *out_perp = expf(-sC[0]);
    }
}

// ---------------- launch ----------------
extern "C" void kernel_launch(void* const* d_in, const int* in_sizes, int n_in,
                              void* d_out, int out_size) {
    const float* x = (const float*)d_in[0];
    const float* e = (const float*)d_in[1];
    float* out = (float*)d_out;

    int N = in_sizes[0] / D;   // 65536
    int K = in_sizes[1] / D;   // 2048
    if (N > MAXN) N = MAXN;
    if (K > MAXK) K = MAXK;

    float* out_q    = out;
    float* out_loss = out + (size_t)N * D;
    float* out_perp = out_loss + 1;
    float* out_idx  = out_perp + 1;

    cudaFuncSetAttribute(k_argmin_mma, cudaFuncAttributeMaxDynamicSharedMemorySize, SMEM_MMA);

    int nx4 = N * (D / 4);
    int ne4 = K * (D / 4);

    k_init   <<<(K + 255) / 256, 256>>>(K);
    k_prep   <<<(K + 7) / 8, 256>>>(e, K);
    k_xsq    <<<(N + 7) / 8, 256>>>(x, N);
    k_split_x<<<(nx4 + 255) / 256, 256>>>((const float4*)x, nx4);
    k_split_e<<<(ne4 + 255) / 256, 256>>>((const float4*)e, ne4);
    k_argmin_mma<<<N / 128, 256, SMEM_MMA>>>(N, K);
    k_gather <<<N / 16, 256>>>(x, e, out_q, out_idx, N);
    k_sim    <<<dim3(K / TN, K / TM), 256>>>(e, K);
    k_final  <<<1, 256>>>(out_loss, out_perp, N, K);
}

// round 6
// speedup vs baseline: 3.9654x; 1.6638x over previous
#include <cuda_runtime.h>
#include <cstdint>

#define D    256
#define MAXK 2048
#define MAXN 65536

#define COMMIT_COST 0.25f
#define DIV_GAMMA   0.1f
#define EPS_F       1e-8f

typedef unsigned long long ull;

// ---------------- device scratch ----------------
__device__ float g_esq[MAXK];
__device__ float g_rninv[MAXK];
__device__ float g_xsq[MAXN];
__device__ int   g_idx[MAXN];
__device__ float g_counts[MAXK];
__device__ float g_acc[4];

// tf32 hi/lo splits
__device__ float4 g_xhi[MAXN * D / 4];
__device__ float4 g_xlo[MAXN * D / 4];
__device__ float4 g_ehi[MAXK * D / 4];
__device__ float4 g_elo[MAXK * D / 4];

// ---------------- helpers ----------------
__device__ __forceinline__ uint32_t smem_u32(const void* p) {
    uint32_t a;
    asm("{ .reg .u64 t; cvta.to.shared.u64 t, %1; cvt.u32.u64 %0, t; }" : "=r"(a) : "l"(p));
    return a;
}
__device__ __forceinline__ float tf32r(float v) {
    uint32_t u;
    asm("cvt.rna.tf32.f32 %0, %1;" : "=r"(u) : "f"(v));
    return __uint_as_float(u);
}
__device__ __forceinline__ void ldsm_x4(uint32_t& d0, uint32_t& d1, uint32_t& d2, uint32_t& d3,
                                        uint32_t addr) {
    asm volatile("ldmatrix.sync.aligned.m8n8.x4.shared.b16 {%0,%1,%2,%3}, [%4];"
        : "=r"(d0), "=r"(d1), "=r"(d2), "=r"(d3) : "r"(addr));
}
__device__ __forceinline__ void mma_tf32(float* c, const uint32_t* a, const uint32_t* b) {
    asm volatile(
        "mma.sync.aligned.m16n8k8.row.col.f32.tf32.tf32.f32 "
        "{%0,%1,%2,%3}, {%4,%5,%6,%7}, {%8,%9}, {%0,%1,%2,%3};"
        : "+f"(c[0]), "+f"(c[1]), "+f"(c[2]), "+f"(c[3])
        : "r"(a[0]), "r"(a[1]), "r"(a[2]), "r"(a[3]), "r"(b[0]), "r"(b[1]));
}
__device__ __forceinline__ void cp16(uint32_t dst, const void* src) {
    asm volatile("{ .reg .u64 g; cvta.to.global.u64 g, %1; "
                 "cp.async.cg.shared.global [%0], [g], 16; }"
                 :: "r"(dst), "l"(src) : "memory");
}
#define CP_COMMIT() asm volatile("cp.async.commit_group;" ::: "memory")
#define CP_WAIT0()  asm volatile("cp.async.wait_group 0;" ::: "memory")

// ---------------- k_init ----------------
__global__ void k_init(int K) {
    int i = blockIdx.x * blockDim.x + threadIdx.x;
    if (i < K) g_counts[i] = 0.f;
    if (i < 4) g_acc[i] = 0.f;
}

// ---------------- k_prep ----------------
__global__ void k_prep(const float* __restrict__ e, int K) {
    int w    = (blockIdx.x * blockDim.x + threadIdx.x) >> 5;
    int lane = threadIdx.x & 31;
    if (w >= K) return;
    const float4* er = reinterpret_cast<const float4*>(e + (size_t)w * D);
    float4 a = er[lane], b = er[32 + lane];
    float s = __fadd_rn(
        __fadd_rn(__fadd_rn(__fmul_rn(a.x,a.x), __fmul_rn(a.y,a.y)),
                  __fadd_rn(__fmul_rn(a.z,a.z), __fmul_rn(a.w,a.w))),
        __fadd_rn(__fadd_rn(__fmul_rn(b.x,b.x), __fmul_rn(b.y,b.y)),
                  __fadd_rn(__fmul_rn(b.z,b.z), __fmul_rn(b.w,b.w))));
#pragma unroll
    for (int off = 16; off > 0; off >>= 1) s += __shfl_xor_sync(0xffffffffu, s, off);
    if (lane == 0) {
        g_esq[w] = s;
        float rn = sqrtf(s);
        g_rninv[w] = 1.0f / fmaxf(rn, 1e-12f);
        atomicAdd(&g_acc[2], rn);
    }
}

// ---------------- k_xsq ----------------
__global__ void k_xsq(const float* __restrict__ x, int N) {
    int w    = (blockIdx.x * blockDim.x + threadIdx.x) >> 5;
    int lane = threadIdx.x & 31;
    if (w >= N) return;
    const float4* xr = reinterpret_cast<const float4*>(x + (size_t)w * D);
    float4 a = xr[lane], b = xr[32 + lane];
    float s = __fadd_rn(
        __fadd_rn(__fadd_rn(__fmul_rn(a.x,a.x), __fmul_rn(a.y,a.y)),
                  __fadd_rn(__fmul_rn(a.z,a.z), __fmul_rn(a.w,a.w))),
        __fadd_rn(__fadd_rn(__fmul_rn(b.x,b.x), __fmul_rn(b.y,b.y)),
                  __fadd_rn(__fmul_rn(b.z,b.z), __fmul_rn(b.w,b.w))));
#pragma unroll
    for (int off = 16; off > 0; off >>= 1) s += __shfl_xor_sync(0xffffffffu, s, off);
    if (lane == 0) g_xsq[w] = s;
}

// ---------------- k_split ----------------
__device__ __forceinline__ void split4(float4 v, float4& h, float4& l) {
    h.x = tf32r(v.x); l.x = tf32r(v.x - h.x);
    h.y = tf32r(v.y); l.y = tf32r(v.y - h.y);
    h.z = tf32r(v.z); l.z = tf32r(v.z - h.z);
    h.w = tf32r(v.w); l.w = tf32r(v.w - h.w);
}
__global__ void k_split_x(const float4* __restrict__ src, int n4) {
    int i = blockIdx.x * blockDim.x + threadIdx.x;
    if (i >= n4) return;
    float4 h, l; split4(src[i], h, l);
    g_xhi[i] = h; g_xlo[i] = l;
}
__global__ void k_split_e(const float4* __restrict__ src, int n4) {
    int i = blockIdx.x * blockDim.x + threadIdx.x;
    if (i >= n4) return;
    float4 h, l; split4(src[i], h, l);
    g_ehi[i] = h; g_elo[i] = l;
}

// ================= pipelined tf32x3 MMA machinery =================
// stage layout (64KB): AHI[16K] ALO[16K] BHI[16K] BLO[16K]; 2 stages; aux @131072
#define STG_SZ   65536
#define S_AHI    0
#define S_ALO    16384
#define S_BHI    32768
#define S_BLO    49152
#define OFF_AUX  131072
#define SMEM_BIG (131072 + 2048)

// async-load one chunk (A: 128 rows x 32f hi/lo from ah/al; B likewise from bh/bl)
__device__ __forceinline__ void stage_load(uint32_t sb,
                                           const float4* __restrict__ ah,
                                           const float4* __restrict__ al,
                                           const float4* __restrict__ bh,
                                           const float4* __restrict__ bl,
                                           int abase_f4, int bbase_f4, int tid) {
#pragma unroll
    for (int rep = 0; rep < 4; rep++) {
        int id   = tid + rep * 256;            // 0..1023
        int row  = id >> 3;
        int g    = id & 7;
        uint32_t so = row * 128 + (g ^ (row & 7)) * 16;
        int fa = abase_f4 + row * 64 + g;
        int fb = bbase_f4 + row * 64 + g;
        cp16(sb + S_AHI + so, ah + fa);
        cp16(sb + S_ALO + so, al + fa);
        cp16(sb + S_BHI + so, bh + fb);
        cp16(sb + S_BLO + so, bl + fb);
    }
}

// per-warp fragment addressing precompute
struct Frag {
    int aoff[4], akey[4], boff[2], bkey[2];
    int asub, bsub;
};
__device__ __forceinline__ void frag_init(Frag& f, int lane, int wm, int wn) {
    f.asub = lane >> 4;
    f.bsub = (lane >> 3) & 1;
#pragma unroll
    for (int ma = 0; ma < 4; ma++) {
        int row = wm * 64 + ma * 16 + ((lane >> 3) & 1) * 8 + (lane & 7);
        f.aoff[ma] = row * 128;
        f.akey[ma] = row & 7;
    }
#pragma unroll
    for (int nb = 0; nb < 2; nb++) {
        int row = wn * 32 + nb * 16 + ((lane >> 4) & 1) * 8 + (lane & 7);
        f.boff[nb] = row * 128;
        f.bkey[nb] = row & 7;
    }
}

// compute one 128x128x32 chunk: acc += xh*eh + xh*el + xl*eh   (tf32x3)
__device__ __forceinline__ void chunk_compute(uint32_t sb, const Frag& f,
                                              float acc[4][4][4]) {
#pragma unroll
    for (int ks = 0; ks < 4; ks++) {
        int ga = ks * 2 + f.asub;
        int gb = ks * 2 + f.bsub;
        uint32_t ah[4][4], al[4][4], bh[4][2], bl[4][2];
#pragma unroll
        for (int ma = 0; ma < 4; ma++)
            ldsm_x4(ah[ma][0], ah[ma][1], ah[ma][2], ah[ma][3],
                    sb + S_AHI + f.aoff[ma] + (((ga ^ f.akey[ma]) & 7) << 4));
#pragma unroll
        for (int nb = 0; nb < 2; nb++) {
            uint32_t d0, d1, d2, d3;
            ldsm_x4(d0, d1, d2, d3,
                    sb + S_BHI + f.boff[nb] + (((gb ^ f.bkey[nb]) & 7) << 4));
            bh[2*nb][0] = d0; bh[2*nb][1] = d1;
            bh[2*nb+1][0] = d2; bh[2*nb+1][1] = d3;
        }
#pragma unroll
        for (int ma = 0; ma < 4; ma++)
#pragma unroll
            for (int na = 0; na < 4; na++)
                mma_tf32(acc[ma][na], ah[ma], bh[na]);
#pragma unroll
        for (int nb = 0; nb < 2; nb++) {
            uint32_t d0, d1, d2, d3;
            ldsm_x4(d0, d1, d2, d3,
                    sb + S_BLO + f.boff[nb] + (((gb ^ f.bkey[nb]) & 7) << 4));
            bl[2*nb][0] = d0; bl[2*nb][1] = d1;
            bl[2*nb+1][0] = d2; bl[2*nb+1][1] = d3;
        }
#pragma unroll
        for (int ma = 0; ma < 4; ma++)
#pragma unroll
            for (int na = 0; na < 4; na++)
                mma_tf32(acc[ma][na], ah[ma], bl[na]);
#pragma unroll
        for (int ma = 0; ma < 4; ma++)
            ldsm_x4(al[ma][0], al[ma][1], al[ma][2], al[ma][3],
                    sb + S_ALO + f.aoff[ma] + (((ga ^ f.akey[ma]) & 7) << 4));
#pragma unroll
        for (int ma = 0; ma < 4; ma++)
#pragma unroll
            for (int na = 0; na < 4; na++)
                mma_tf32(acc[ma][na], al[ma], bh[na]);
    }
}

// ---------------- k_argmin_mma ----------------
__global__ void __launch_bounds__(256, 1)
k_argmin_mma(int N, int K) {
    extern __shared__ char dsm[];
    uint32_t smb = smem_u32(dsm);
    int tid  = threadIdx.x;
    int lane = tid & 31;
    int wid  = tid >> 5;
    int wm   = wid >> 2;
    int wn   = wid & 3;
    int m0   = blockIdx.x * 128;

    Frag f; frag_init(f, lane, wm, wn);

    ull tbest[8];
#pragma unroll
    for (int i = 0; i < 8; i++) tbest[i] = 0xFFFFFFFFFFFFFFFFULL;

    int NT = K / 128;
    int C  = NT * 8;

    // prologue: load chunk 0
    stage_load(smb, g_xhi, g_xlo, g_ehi, g_elo, m0 * 64, 0, tid);
    CP_COMMIT();

    float acc[4][4][4];
#pragma unroll
    for (int ma = 0; ma < 4; ma++)
#pragma unroll
        for (int na = 0; na < 4; na++)
#pragma unroll
            for (int c = 0; c < 4; c++) acc[ma][na][c] = 0.f;

#pragma unroll 1
    for (int c = 0; c < C; c++) {
        int nt = c >> 3, dc = c & 7;
        uint32_t sb = smb + (c & 1) * STG_SZ;

        CP_WAIT0();
        __syncthreads();

        if (c + 1 < C) {
            int nt1 = (c + 1) >> 3, dc1 = (c + 1) & 7;
            stage_load(smb + ((c + 1) & 1) * STG_SZ, g_xhi, g_xlo, g_ehi, g_elo,
                       m0 * 64 + dc1 * 8, nt1 * 128 * 64 + dc1 * 8, tid);
            CP_COMMIT();
        } else {
            CP_COMMIT();   // empty group keeps wait_group accounting uniform
        }

        chunk_compute(sb, f, acc);

        if (dc == 7) {
            // epilogue for this n-tile
#pragma unroll
            for (int ma = 0; ma < 4; ma++) {
                int m_r = m0 + wm * 64 + ma * 16 + (lane >> 2);
                float xq0 = g_xsq[m_r];
                float xq1 = g_xsq[m_r + 8];
#pragma unroll
                for (int na = 0; na < 4; na++) {
                    int n0c = nt * 128 + wn * 32 + na * 8 + 2 * (lane & 3);
                    float e0 = g_esq[n0c], e1 = g_esq[n0c + 1];
                    float d00 = __fsub_rn(__fadd_rn(xq0, e0), 2.0f * acc[ma][na][0]);
                    float d01 = __fsub_rn(__fadd_rn(xq0, e1), 2.0f * acc[ma][na][1]);
                    float d10 = __fsub_rn(__fadd_rn(xq1, e0), 2.0f * acc[ma][na][2]);
                    float d11 = __fsub_rn(__fadd_rn(xq1, e1), 2.0f * acc[ma][na][3]);
                    ull c00 = ((ull)__float_as_uint(d00) << 32) | (unsigned)n0c;
                    ull c01 = ((ull)__float_as_uint(d01) << 32) | (unsigned)(n0c + 1);
                    ull c10 = ((ull)__float_as_uint(d10) << 32) | (unsigned)n0c;
                    ull c11 = ((ull)__float_as_uint(d11) << 32) | (unsigned)(n0c + 1);
                    if (c00 < tbest[ma * 2])     tbest[ma * 2] = c00;
                    if (c01 < tbest[ma * 2])     tbest[ma * 2] = c01;
                    if (c10 < tbest[ma * 2 + 1]) tbest[ma * 2 + 1] = c10;
                    if (c11 < tbest[ma * 2 + 1]) tbest[ma * 2 + 1] = c11;
                    acc[ma][na][0] = 0.f; acc[ma][na][1] = 0.f;
                    acc[ma][na][2] = 0.f; acc[ma][na][3] = 0.f;
                }
            }
        }
    }

    // cross-thread argmin
    ull* best = reinterpret_cast<ull*>(dsm + OFF_AUX);
    __syncthreads();
    if (tid < 128) best[tid] = 0xFFFFFFFFFFFFFFFFULL;
    __syncthreads();
#pragma unroll
    for (int ma = 0; ma < 4; ma++) {
        int mloc = wm * 64 + ma * 16 + (lane >> 2);
        atomicMin(&best[mloc],     tbest[ma * 2]);
        atomicMin(&best[mloc + 8], tbest[ma * 2 + 1]);
    }
    __syncthreads();
    if (tid < 128) g_idx[m0 + tid] = (int)(best[tid] & 0xFFFFFFFFu);
}

// ---------------- k_sim_mma: triangular-block cosine-sim sum ----------------
__global__ void __launch_bounds__(256, 1)
k_sim_mma(int K) {
    extern __shared__ char dsm[];
    uint32_t smb = smem_u32(dsm);
    int tid  = threadIdx.x;
    int lane = tid & 31;
    int wid  = tid >> 5;
    int wm   = wid >> 2;
    int wn   = wid & 3;

    // decode triangular block index -> (by, bx), by <= bx
    int nt_blocks = K / 128;
    int b = blockIdx.x, by = 0;
    while (b >= nt_blocks - by) { b -= nt_blocks - by; by++; }
    int bx = by + b;
    int m0 = by * 128, n0 = bx * 128;
    float wgt = (by == bx) ? 1.0f : 2.0f;

    Frag f; frag_init(f, lane, wm, wn);

    float acc[4][4][4];
#pragma unroll
    for (int ma = 0; ma < 4; ma++)
#pragma unroll
        for (int na = 0; na < 4; na++)
#pragma unroll
            for (int c = 0; c < 4; c++) acc[ma][na][c] = 0.f;

    stage_load(smb, g_ehi, g_elo, g_ehi, g_elo, m0 * 64, n0 * 64, tid);
    CP_COMMIT();

#pragma unroll 1
    for (int dc = 0; dc < 8; dc++) {
        uint32_t sb = smb + (dc & 1) * STG_SZ;
        CP_WAIT0();
        __syncthreads();
        if (dc + 1 < 8) {
            stage_load(smb + ((dc + 1) & 1) * STG_SZ, g_ehi, g_elo, g_ehi, g_elo,
                       m0 * 64 + (dc + 1) * 8, n0 * 64 + (dc + 1) * 8, tid);
            CP_COMMIT();
        } else {
            CP_COMMIT();
        }
        chunk_compute(sb, f, acc);
    }

    float s = 0.f;
#pragma unroll
    for (int ma = 0; ma < 4; ma++) {
        int m_r0 = m0 + wm * 64 + ma * 16 + (lane >> 2);
        float r0 = g_rninv[m_r0], r1 = g_rninv[m_r0 + 8];
#pragma unroll
        for (int na = 0; na < 4; na++) {
            int n0c = n0 + wn * 32 + na * 8 + 2 * (lane & 3);
            float q0 = g_rninv[n0c], q1 = g_rninv[n0c + 1];
            float s00 = fabsf(acc[ma][na][0] * r0 * q0);
            float s01 = fabsf(acc[ma][na][1] * r0 * q1);
            float s10 = fabsf(acc[ma][na][2] * r1 * q0);
            float s11 = fabsf(acc[ma][na][3] * r1 * q1);
            if (m_r0     == n0c)     s00 = 0.f;
            if (m_r0     == n0c + 1) s01 = 0.f;
            if (m_r0 + 8 == n0c)     s10 = 0.f;
            if (m_r0 + 8 == n0c + 1) s11 = 0.f;
            s += (s00 + s01) + (s10 + s11);
        }
    }
    s *= wgt;

    float* red = reinterpret_cast<float*>(dsm + OFF_AUX);
    __syncthreads();
    red[tid] = s; __syncthreads();
    for (int st = 128; st > 0; st >>= 1) { if (tid < st) red[tid] += red[tid + st]; __syncthreads(); }
    if (tid == 0) atomicAdd(&g_acc[1], red[0]);
}

// ---------------- k_gather ----------------
__global__ void __launch_bounds__(256)
k_gather(const float* __restrict__ x, const float* __restrict__ e,
         float* __restrict__ outq, float* __restrict__ outidx, int N) {
    __shared__ float red[256];
    int tid = threadIdx.x;
    int t   = blockIdx.x * 16 + (tid >> 4);
    int seg = tid & 15;
    int k = g_idx[t];
    const float4* er = reinterpret_cast<const float4*>(e + (size_t)k * D);
    const float4* xr = reinterpret_cast<const float4*>(x + (size_t)t * D);
    float4* qr = reinterpret_cast<float4*>(outq + (size_t)t * D);
    float s = 0.f;
#pragma unroll
    for (int j = 0; j < 4; j++) {
        int c = seg + j * 16;
        float4 q = er[c], xv = xr[c];
        qr[c] = q;
        float dx = q.x - xv.x, dy = q.y - xv.y, dz = q.z - xv.z, dw = q.w - xv.w;
        s += (dx * dx + dy * dy) + (dz * dz + dw * dw);
    }
    red[tid] = s; __syncthreads();
    for (int st = 128; st > 0; st >>= 1) { if (tid < st) red[tid] += red[tid + st]; __syncthreads(); }
    if (tid == 0) atomicAdd(&g_acc[0], red[0]);
    if (seg == 0) {
        outidx[t] = (float)k;
        atomicAdd(&g_counts[k], 1.0f);
    }
}

// ---------------- k_final ----------------
__global__ void k_final(float* __restrict__ out_loss, float* __restrict__ out_perp, int N, int K) {
    __shared__ float sA[256], sB[256], sC[256];
    int tid = threadIdx.x;

    float tot = 0.f;
    for (int k = tid; k < K; k += 256) tot += g_counts[k];
    sA[tid] = tot; __syncthreads();
    for (int st = 128; st > 0; st >>= 1) { if (tid < st) sA[tid] += sA[tid + st]; __syncthreads(); }
    float total = sA[0];
    __syncthreads();

    float tuni = 1.0f / (float)K;
    float kl = 0.f, pl = 0.f;
    for (int k = tid; k < K; k += 256) {
        float p = g_counts[k] / total;
        kl += (p + EPS_F) * logf((p + EPS_F) / (tuni + EPS_F));
        if (p > 0.f) pl += p * logf(p);
    }
    sB[tid] = kl; sC[tid] = pl; __syncthreads();
    for (int st = 128; st > 0; st >>= 1) {
        if (tid < st) { sB[tid] += sB[tid + st]; sC[tid] += sC[tid + st]; }
        __syncthreads();
    }
    if (tid == 0) {
        float klv = fminf(sB[0], 100.0f);
        float mse = g_acc[0] / ((float)N * (float)D);
        float vq  = mse + COMMIT_COST * mse;
        float l2  = fminf(g_acc[2] / (float)K, 10.0f);
        float orth = fminf(g_acc[1] / ((float)K * (float)K), 10.0f);
        float reg = l2 + orth;
        float loss = fminf(vq + DIV_GAMMA * klv + 0.01f * reg, 100.0f);
        *out_loss = loss;
        *out_perp = expf(-sC[0]);
    }
}

// ---------------- launch ----------------
extern "C" void kernel_launch(void* const* d_in, const int* in_sizes, int n_in,
                              void* d_out, int out_size) {
    const float* x = (const float*)d_in[0];
    const float* e = (const float*)d_in[1];
    float* out = (float*)d_out;

    int N = in_sizes[0] / D;   // 65536
    int K = in_sizes[1] / D;   // 2048
    if (N > MAXN) N = MAXN;
    if (K > MAXK) K = MAXK;

    float* out_q    = out;
    float* out_loss = out + (size_t)N * D;
    float* out_perp = out_loss + 1;
    float* out_idx  = out_perp + 1;

    cudaFuncSetAttribute(k_argmin_mma, cudaFuncAttributeMaxDynamicSharedMemorySize, SMEM_BIG);
    cudaFuncSetAttribute(k_sim_mma,    cudaFuncAttributeMaxDynamicSharedMemorySize, SMEM_BIG);

    int nx4 = N * (D / 4);
    int ne4 = K * (D / 4);
    int ntb = K / 128;
    int tri = ntb * (ntb + 1) / 2;

    k_init   <<<(K + 255) / 256, 256>>>(K);
    k_prep   <<<(K + 7) / 8, 256>>>(e, K);
    k_xsq    <<<(N + 7) / 8, 256>>>(x, N);
    k_split_x<<<(nx4 + 255) / 256, 256>>>((const float4*)x, nx4);
    k_split_e<<<(ne4 + 255) / 256, 256>>>((const float4*)e, ne4);
    k_argmin_mma<<<N / 128, 256, SMEM_BIG>>>(N, K);
    k_gather <<<N / 16, 256>>>(x, e, out_q, out_idx, N);
    k_sim_mma<<<tri, 256, SMEM_BIG>>>(K);
    k_final  <<<1, 256>>>(out_loss, out_perp, N, K);
}

// round 7
// speedup vs baseline: 6.9247x; 1.7463x over previous
#include <cuda_runtime.h>
#include <cuda_bf16.h>
#include <cstdint>

#define D    256
#define MAXK 2048
#define MAXN 65536

#define COMMIT_COST 0.25f
#define DIV_GAMMA   0.1f
#define EPS_F       1e-8f

typedef unsigned long long ull;

// ---------------- device scratch ----------------
__device__ float g_esq[MAXK];
__device__ float g_rninv[MAXK];
__device__ float g_xsq[MAXN];
__device__ int   g_idx[MAXN];
__device__ float g_counts[MAXK];
__device__ float g_acc[4];

// bf16 hi/lo splits, stored as 16B granules (8 bf16 each)
__device__ uint4 g_xhi[MAXN * D / 8];
__device__ uint4 g_xlo[MAXN * D / 8];
__device__ uint4 g_ehi[MAXK * D / 8];
__device__ uint4 g_elo[MAXK * D / 8];

// ---------------- helpers ----------------
__device__ __forceinline__ uint32_t smem_u32(const void* p) {
    uint32_t a;
    asm("{ .reg .u64 t; cvta.to.shared.u64 t, %1; cvt.u32.u64 %0, t; }" : "=r"(a) : "l"(p));
    return a;
}
__device__ __forceinline__ void ldsm_x4(uint32_t& d0, uint32_t& d1, uint32_t& d2, uint32_t& d3,
                                        uint32_t addr) {
    asm volatile("ldmatrix.sync.aligned.m8n8.x4.shared.b16 {%0,%1,%2,%3}, [%4];"
        : "=r"(d0), "=r"(d1), "=r"(d2), "=r"(d3) : "r"(addr));
}
__device__ __forceinline__ void mma_bf16(float* c, const uint32_t* a, const uint32_t* b) {
    asm volatile(
        "mma.sync.aligned.m16n8k16.row.col.f32.bf16.bf16.f32 "
        "{%0,%1,%2,%3}, {%4,%5,%6,%7}, {%8,%9}, {%0,%1,%2,%3};"
        : "+f"(c[0]), "+f"(c[1]), "+f"(c[2]), "+f"(c[3])
        : "r"(a[0]), "r"(a[1]), "r"(a[2]), "r"(a[3]), "r"(b[0]), "r"(b[1]));
}
__device__ __forceinline__ void cp16(uint32_t dst, const void* src) {
    asm volatile("{ .reg .u64 g; cvta.to.global.u64 g, %1; "
                 "cp.async.cg.shared.global [%0], [g], 16; }"
                 :: "r"(dst), "l"(src) : "memory");
}
#define CP_COMMIT() asm volatile("cp.async.commit_group;" ::: "memory")
#define CP_WAIT0()  asm volatile("cp.async.wait_group 0;" ::: "memory")

// ---------------- k_init ----------------
__global__ void k_init(int K) {
    int i = blockIdx.x * blockDim.x + threadIdx.x;
    if (i < K) g_counts[i] = 0.f;
    if (i < 4) g_acc[i] = 0.f;
}

// ---------------- k_prep ----------------
__global__ void k_prep(const float* __restrict__ e, int K) {
    int w    = (blockIdx.x * blockDim.x + threadIdx.x) >> 5;
    int lane = threadIdx.x & 31;
    if (w >= K) return;
    const float4* er = reinterpret_cast<const float4*>(e + (size_t)w * D);
    float4 a = er[lane], b = er[32 + lane];
    float s = __fadd_rn(
        __fadd_rn(__fadd_rn(__fmul_rn(a.x,a.x), __fmul_rn(a.y,a.y)),
                  __fadd_rn(__fmul_rn(a.z,a.z), __fmul_rn(a.w,a.w))),
        __fadd_rn(__fadd_rn(__fmul_rn(b.x,b.x), __fmul_rn(b.y,b.y)),
                  __fadd_rn(__fmul_rn(b.z,b.z), __fmul_rn(b.w,b.w))));
#pragma unroll
    for (int off = 16; off > 0; off >>= 1) s += __shfl_xor_sync(0xffffffffu, s, off);
    if (lane == 0) {
        g_esq[w] = s;
        float rn = sqrtf(s);
        g_rninv[w] = 1.0f / fmaxf(rn, 1e-12f);
        atomicAdd(&g_acc[2], rn);
    }
}

// ---------------- k_xsq ----------------
__global__ void k_xsq(const float* __restrict__ x, int N) {
    int w    = (blockIdx.x * blockDim.x + threadIdx.x) >> 5;
    int lane = threadIdx.x & 31;
    if (w >= N) return;
    const float4* xr = reinterpret_cast<const float4*>(x + (size_t)w * D);
    float4 a = xr[lane], b = xr[32 + lane];
    float s = __fadd_rn(
        __fadd_rn(__fadd_rn(__fmul_rn(a.x,a.x), __fmul_rn(a.y,a.y)),
                  __fadd_rn(__fmul_rn(a.z,a.z), __fmul_rn(a.w,a.w))),
        __fadd_rn(__fadd_rn(__fmul_rn(b.x,b.x), __fmul_rn(b.y,b.y)),
                  __fadd_rn(__fmul_rn(b.z,b.z), __fmul_rn(b.w,b.w))));
#pragma unroll
    for (int off = 16; off > 0; off >>= 1) s += __shfl_xor_sync(0xffffffffu, s, off);
    if (lane == 0) g_xsq[w] = s;
}

// ---------------- k_split: bf16 hi/lo (granule = 8 elems = 16B) ----------------
__device__ __forceinline__ void split8(const float* f, uint4& hh, uint4& ll) {
    unsigned h[8], l[8];
#pragma unroll
    for (int j = 0; j < 8; j++) {
        __nv_bfloat16 hb = __float2bfloat16(f[j]);
        float hf = __bfloat162float(hb);
        __nv_bfloat16 lb = __float2bfloat16(f[j] - hf);
        h[j] = __bfloat16_as_ushort(hb);
        l[j] = __bfloat16_as_ushort(lb);
    }
    hh = make_uint4(h[0] | (h[1] << 16), h[2] | (h[3] << 16),
                    h[4] | (h[5] << 16), h[6] | (h[7] << 16));
    ll = make_uint4(l[0] | (l[1] << 16), l[2] | (l[3] << 16),
                    l[4] | (l[5] << 16), l[6] | (l[7] << 16));
}
__global__ void k_split_x(const float4* __restrict__ src, int n8) {
    int i = blockIdx.x * blockDim.x + threadIdx.x;
    if (i >= n8) return;
    float4 v0 = src[2 * i], v1 = src[2 * i + 1];
    float f[8] = {v0.x, v0.y, v0.z, v0.w, v1.x, v1.y, v1.z, v1.w};
    uint4 hh, ll; split8(f, hh, ll);
    g_xhi[i] = hh; g_xlo[i] = ll;
}
__global__ void k_split_e(const float4* __restrict__ src, int n8) {
    int i = blockIdx.x * blockDim.x + threadIdx.x;
    if (i >= n8) return;
    float4 v0 = src[2 * i], v1 = src[2 * i + 1];
    float f[8] = {v0.x, v0.y, v0.z, v0.w, v1.x, v1.y, v1.z, v1.w};
    uint4 hh, ll; split8(f, hh, ll);
    g_ehi[i] = hh; g_elo[i] = ll;
}

// ================= pipelined bf16x3 MMA machinery =================
// chunk = 128 rows x 32 k (bf16, 64B/row). Physical layout folds 2 rows per 128B line:
//   phys(row,g) = (row>>1)*128 + (row&1)*64 + ((g ^ ((row>>1)&3)) << 4),  g = k granule 0..3
// stage (32KB): AHI[8K] ALO[8K] BHI[8K] BLO[8K]; 2 stages; aux @65536
#define STG_SZ   32768
#define S_AHI    0
#define S_ALO    8192
#define S_BHI    16384
#define S_BLO    24576
#define OFF_AUX  65536
#define SMEM_BIG (65536 + 2048)

__device__ __forceinline__ void stage_load(uint32_t sb,
                                           const uint4* __restrict__ ah,
                                           const uint4* __restrict__ al,
                                           const uint4* __restrict__ bh,
                                           const uint4* __restrict__ bl,
                                           int abase_g, int bbase_g, int tid) {
#pragma unroll
    for (int rep = 0; rep < 2; rep++) {
        int id  = tid + rep * 256;             // 0..511
        int row = id >> 2;
        int g   = id & 3;
        uint32_t so = (row >> 1) * 128 + (row & 1) * 64 + ((g ^ ((row >> 1) & 3)) << 4);
        int fa = abase_g + row * 32 + g;       // 32 granules per 256-elem row
        int fb = bbase_g + row * 32 + g;
        cp16(sb + S_AHI + so, ah + fa);
        cp16(sb + S_ALO + so, al + fa);
        cp16(sb + S_BHI + so, bh + fb);
        cp16(sb + S_BLO + so, bl + fb);
    }
}

struct Frag {
    int aoff[4], akey[4], boff[2], bkey[2];
    int asub, bsub;
};
__device__ __forceinline__ void frag_init(Frag& f, int lane, int wm, int wn) {
    f.asub = lane >> 4;            // A: k-granule select
    f.bsub = (lane >> 3) & 1;      // B: k-granule select
#pragma unroll
    for (int ma = 0; ma < 4; ma++) {
        int row = wm * 64 + ma * 16 + ((lane >> 3) & 1) * 8 + (lane & 7);
        f.aoff[ma] = (row >> 1) * 128 + (row & 1) * 64;
        f.akey[ma] = (row >> 1) & 3;
    }
#pragma unroll
    for (int pr = 0; pr < 2; pr++) {
        int row = wn * 32 + pr * 16 + ((lane >> 4) & 1) * 8 + (lane & 7);
        f.boff[pr] = (row >> 1) * 128 + (row & 1) * 64;
        f.bkey[pr] = (row >> 1) & 3;
    }
}

// one 128x128x32 chunk: acc += xh*eh + xh*el + xl*eh   (bf16x3, k16 MMAs)
__device__ __forceinline__ void chunk_compute(uint32_t sb, const Frag& f,
                                              float acc[4][4][4]) {
#pragma unroll
    for (int ks = 0; ks < 2; ks++) {
        int ga = ks * 2 + f.asub;
        int gb = ks * 2 + f.bsub;
        uint32_t ah[4][4], al[4][4], bh[4][2], bl[4][2];
#pragma unroll
        for (int ma = 0; ma < 4; ma++)
            ldsm_x4(ah[ma][0], ah[ma][1], ah[ma][2], ah[ma][3],
                    sb + S_AHI + f.aoff[ma] + (((ga ^ f.akey[ma]) & 3) << 4));
#pragma unroll
        for (int pr = 0; pr < 2; pr++) {
            uint32_t d0, d1, d2, d3;
            ldsm_x4(d0, d1, d2, d3,
                    sb + S_BHI + f.boff[pr] + (((gb ^ f.bkey[pr]) & 3) << 4));
            bh[2*pr][0] = d0; bh[2*pr][1] = d1;
            bh[2*pr+1][0] = d2; bh[2*pr+1][1] = d3;
        }
#pragma unroll
        for (int ma = 0; ma < 4; ma++)
#pragma unroll
            for (int na = 0; na < 4; na++)
                mma_bf16(acc[ma][na], ah[ma], bh[na]);
#pragma unroll
        for (int pr = 0; pr < 2; pr++) {
            uint32_t d0, d1, d2, d3;
            ldsm_x4(d0, d1, d2, d3,
                    sb + S_BLO + f.boff[pr] + (((gb ^ f.bkey[pr]) & 3) << 4));
            bl[2*pr][0] = d0; bl[2*pr][1] = d1;
            bl[2*pr+1][0] = d2; bl[2*pr+1][1] = d3;
        }
#pragma unroll
        for (int ma = 0; ma < 4; ma++)
#pragma unroll
            for (int na = 0; na < 4; na++)
                mma_bf16(acc[ma][na], ah[ma], bl[na]);
#pragma unroll
        for (int ma = 0; ma < 4; ma++)
            ldsm_x4(al[ma][0], al[ma][1], al[ma][2], al[ma][3],
                    sb + S_ALO + f.aoff[ma] + (((ga ^ f.akey[ma]) & 3) << 4));
#pragma unroll
        for (int ma = 0; ma < 4; ma++)
#pragma unroll
            for (int na = 0; na < 4; na++)
                mma_bf16(acc[ma][na], al[ma], bh[na]);
    }
}

// ---------------- k_argmin_mma ----------------
__global__ void __launch_bounds__(256, 2)
k_argmin_mma(int N, int K) {
    extern __shared__ char dsm[];
    uint32_t smb = smem_u32(dsm);
    int tid  = threadIdx.x;
    int lane = tid & 31;
    int wid  = tid >> 5;
    int wm   = wid >> 2;
    int wn   = wid & 3;
    int m0   = blockIdx.x * 128;

    Frag f; frag_init(f, lane, wm, wn);

    ull tbest[8];
#pragma unroll
    for (int i = 0; i < 8; i++) tbest[i] = 0xFFFFFFFFFFFFFFFFULL;

    int NT = K / 128;
    int C  = NT * 8;

    stage_load(smb, g_xhi, g_xlo, g_ehi, g_elo, m0 * 32, 0, tid);
    CP_COMMIT();

    float acc[4][4][4];
#pragma unroll
    for (int ma = 0; ma < 4; ma++)
#pragma unroll
        for (int na = 0; na < 4; na++)
#pragma unroll
            for (int c = 0; c < 4; c++) acc[ma][na][c] = 0.f;

#pragma unroll 1
    for (int c = 0; c < C; c++) {
        int nt = c >> 3, dc = c & 7;
        uint32_t sb = smb + (c & 1) * STG_SZ;

        CP_WAIT0();
        __syncthreads();

        if (c + 1 < C) {
            int nt1 = (c + 1) >> 3, dc1 = (c + 1) & 7;
            stage_load(smb + ((c + 1) & 1) * STG_SZ, g_xhi, g_xlo, g_ehi, g_elo,
                       m0 * 32 + dc1 * 4, nt1 * 128 * 32 + dc1 * 4, tid);
            CP_COMMIT();
        } else {
            CP_COMMIT();
        }

        chunk_compute(sb, f, acc);

        if (dc == 7) {
#pragma unroll
            for (int ma = 0; ma < 4; ma++) {
                int m_r = m0 + wm * 64 + ma * 16 + (lane >> 2);
                float xq0 = g_xsq[m_r];
                float xq1 = g_xsq[m_r + 8];
#pragma unroll
                for (int na = 0; na < 4; na++) {
                    int n0c = nt * 128 + wn * 32 + na * 8 + 2 * (lane & 3);
                    float e0 = g_esq[n0c], e1 = g_esq[n0c + 1];
                    float d00 = __fsub_rn(__fadd_rn(xq0, e0), 2.0f * acc[ma][na][0]);
                    float d01 = __fsub_rn(__fadd_rn(xq0, e1), 2.0f * acc[ma][na][1]);
                    float d10 = __fsub_rn(__fadd_rn(xq1, e0), 2.0f * acc[ma][na][2]);
                    float d11 = __fsub_rn(__fadd_rn(xq1, e1), 2.0f * acc[ma][na][3]);
                    ull c00 = ((ull)__float_as_uint(d00) << 32) | (unsigned)n0c;
                    ull c01 = ((ull)__float_as_uint(d01) << 32) | (unsigned)(n0c + 1);
                    ull c10 = ((ull)__float_as_uint(d10) << 32) | (unsigned)n0c;
                    ull c11 = ((ull)__float_as_uint(d11) << 32) | (unsigned)(n0c + 1);
                    if (c00 < tbest[ma * 2])     tbest[ma * 2] = c00;
                    if (c01 < tbest[ma * 2])     tbest[ma * 2] = c01;
                    if (c10 < tbest[ma * 2 + 1]) tbest[ma * 2 + 1] = c10;
                    if (c11 < tbest[ma * 2 + 1]) tbest[ma * 2 + 1] = c11;
                    acc[ma][na][0] = 0.f; acc[ma][na][1] = 0.f;
                    acc[ma][na][2] = 0.f; acc[ma][na][3] = 0.f;
                }
            }
        }
    }

    ull* best = reinterpret_cast<ull*>(dsm + OFF_AUX);
    __syncthreads();
    if (tid < 128) best[tid] = 0xFFFFFFFFFFFFFFFFULL;
    __syncthreads();
#pragma unroll
    for (int ma = 0; ma < 4; ma++) {
        int mloc = wm * 64 + ma * 16 + (lane >> 2);
        atomicMin(&best[mloc],     tbest[ma * 2]);
        atomicMin(&best[mloc + 8], tbest[ma * 2 + 1]);
    }
    __syncthreads();
    if (tid < 128) g_idx[m0 + tid] = (int)(best[tid] & 0xFFFFFFFFu);
}

// ---------------- k_sim_mma ----------------
__global__ void __launch_bounds__(256, 2)
k_sim_mma(int K) {
    extern __shared__ char dsm[];
    uint32_t smb = smem_u32(dsm);
    int tid  = threadIdx.x;
    int lane = tid & 31;
    int wid  = tid >> 5;
    int wm   = wid >> 2;
    int wn   = wid & 3;

    int nt_blocks = K / 128;
    int b = blockIdx.x, by = 0;
    while (b >= nt_blocks - by) { b -= nt_blocks - by; by++; }
    int bx = by + b;
    int m0 = by * 128, n0 = bx * 128;
    float wgt = (by == bx) ? 1.0f : 2.0f;

    Frag f; frag_init(f, lane, wm, wn);

    float acc[4][4][4];
#pragma unroll
    for (int ma = 0; ma < 4; ma++)
#pragma unroll
        for (int na = 0; na < 4; na++)
#pragma unroll
            for (int c = 0; c < 4; c++) acc[ma][na][c] = 0.f;

    stage_load(smb, g_ehi, g_elo, g_ehi, g_elo, m0 * 32, n0 * 32, tid);
    CP_COMMIT();

#pragma unroll 1
    for (int dc = 0; dc < 8; dc++) {
        uint32_t sb = smb + (dc & 1) * STG_SZ;
        CP_WAIT0();
        __syncthreads();
        if (dc + 1 < 8) {
            stage_load(smb + ((dc + 1) & 1) * STG_SZ, g_ehi, g_elo, g_ehi, g_elo,
                       m0 * 32 + (dc + 1) * 4, n0 * 32 + (dc + 1) * 4, tid);
            CP_COMMIT();
        } else {
            CP_COMMIT();
        }
        chunk_compute(sb, f, acc);
    }

    float s = 0.f;
#pragma unroll
    for (int ma = 0; ma < 4; ma++) {
        int m_r0 = m0 + wm * 64 + ma * 16 + (lane >> 2);
        float r0 = g_rninv[m_r0], r1 = g_rninv[m_r0 + 8];
#pragma unroll
        for (int na = 0; na < 4; na++) {
            int n0c = n0 + wn * 32 + na * 8 + 2 * (lane & 3);
            float q0 = g_rninv[n0c], q1 = g_rninv[n0c + 1];
            float s00 = fabsf(acc[ma][na][0] * r0 * q0);
            float s01 = fabsf(acc[ma][na][1] * r0 * q1);
            float s10 = fabsf(acc[ma][na][2] * r1 * q0);
            float s11 = fabsf(acc[ma][na][3] * r1 * q1);
            if (m_r0     == n0c)     s00 = 0.f;
            if (m_r0     == n0c + 1) s01 = 0.f;
            if (m_r0 + 8 == n0c)     s10 = 0.f;
            if (m_r0 + 8 == n0c + 1) s11 = 0.f;
            s += (s00 + s01) + (s10 + s11);
        }
    }
    s *= wgt;

    float* red = reinterpret_cast<float*>(dsm + OFF_AUX);
    __syncthreads();
    red[tid] = s; __syncthreads();
    for (int st = 128; st > 0; st >>= 1) { if (tid < st) red[tid] += red[tid + st]; __syncthreads(); }
    if (tid == 0) atomicAdd(&g_acc[1], red[0]);
}

// ---------------- k_gather ----------------
__global__ void __launch_bounds__(256)
k_gather(const float* __restrict__ x, const float* __restrict__ e,
         float* __restrict__ outq, float* __restrict__ outidx, int N) {
    __shared__ float red[256];
    int tid = threadIdx.x;
    int t   = blockIdx.x * 16 + (tid >> 4);
    int seg = tid & 15;
    int k = g_idx[t];
    const float4* er = reinterpret_cast<const float4*>(e + (size_t)k * D);
    const float4* xr = reinterpret_cast<const float4*>(x + (size_t)t * D);
    float4* qr = reinterpret_cast<float4*>(outq + (size_t)t * D);
    float s = 0.f;
#pragma unroll
    for (int j = 0; j < 4; j++) {
        int c = seg + j * 16;
        float4 q = er[c], xv = xr[c];
        qr[c] = q;
        float dx = q.x - xv.x, dy = q.y - xv.y, dz = q.z - xv.z, dw = q.w - xv.w;
        s += (dx * dx + dy * dy) + (dz * dz + dw * dw);
    }
    red[tid] = s; __syncthreads();
    for (int st = 128; st > 0; st >>= 1) { if (tid < st) red[tid] += red[tid + st]; __syncthreads(); }
    if (tid == 0) atomicAdd(&g_acc[0], red[0]);
    if (seg == 0) {
        outidx[t] = (float)k;
        atomicAdd(&g_counts[k], 1.0f);
    }
}

// ---------------- k_final ----------------
__global__ void k_final(float* __restrict__ out_loss, float* __restrict__ out_perp, int N, int K) {
    __shared__ float sA[256], sB[256], sC[256];
    int tid = threadIdx.x;

    float tot = 0.f;
    for (int k = tid; k < K; k += 256) tot += g_counts[k];
    sA[tid] = tot; __syncthreads();
    for (int st = 128; st > 0; st >>= 1) { if (tid < st) sA[tid] += sA[tid + st]; __syncthreads(); }
    float total = sA[0];
    __syncthreads();

    float tuni = 1.0f / (float)K;
    float kl = 0.f, pl = 0.f;
    for (int k = tid; k < K; k += 256) {
        float p = g_counts[k] / total;
        kl += (p + EPS_F) * logf((p + EPS_F) / (tuni + EPS_F));
        if (p > 0.f) pl += p * logf(p);
    }
    sB[tid] = kl; sC[tid] = pl; __syncthreads();
    for (int st = 128; st > 0; st >>= 1) {
        if (tid < st) { sB[tid] += sB[tid + st]; sC[tid] += sC[tid + st]; }
        __syncthreads();
    }
    if (tid == 0) {
        float klv = fminf(sB[0], 100.0f);
        float mse = g_acc[0] / ((float)N * (float)D);
        float vq  = mse + COMMIT_COST * mse;
        float l2  = fminf(g_acc[2] / (float)K, 10.0f);
        float orth = fminf(g_acc[1] / ((float)K * (float)K), 10.0f);
        float reg = l2 + orth;
        float loss = fminf(vq + DIV_GAMMA * klv + 0.01f * reg, 100.0f);
        *out_loss = loss;
        *out_perp = expf(-sC[0]);
    }
}

// ---------------- launch ----------------
extern "C" void kernel_launch(void* const* d_in, const int* in_sizes, int n_in,
                              void* d_out, int out_size) {
    const float* x = (const float*)d_in[0];
    const float* e = (const float*)d_in[1];
    float* out = (float*)d_out;

    int N = in_sizes[0] / D;   // 65536
    int K = in_sizes[1] / D;   // 2048
    if (N > MAXN) N = MAXN;
    if (K > MAXK) K = MAXK;

    float* out_q    = out;
    float* out_loss = out + (size_t)N * D;
    float* out_perp = out_loss + 1;
    float* out_idx  = out_perp + 1;

    cudaFuncSetAttribute(k_argmin_mma, cudaFuncAttributeMaxDynamicSharedMemorySize, SMEM_BIG);
    cudaFuncSetAttribute(k_sim_mma,    cudaFuncAttributeMaxDynamicSharedMemorySize, SMEM_BIG);

    int nx8 = N * (D / 8);
    int ne8 = K * (D / 8);
    int ntb = K / 128;
    int tri = ntb * (ntb + 1) / 2;

    k_init   <<<(K + 255) / 256, 256>>>(K);
    k_prep   <<<(K + 7) / 8, 256>>>(e, K);
    k_xsq    <<<(N + 7) / 8, 256>>>(x, N);
    k_split_x<<<(nx8 + 255) / 256, 256>>>((const float4*)x, nx8);
    k_split_e<<<(ne8 + 255) / 256, 256>>>((const float4*)e, ne8);
    k_argmin_mma<<<N / 128, 256, SMEM_BIG>>>(N, K);
    k_gather <<<N / 16, 256>>>(x, e, out_q, out_idx, N);
    k_sim_mma<<<tri, 256, SMEM_BIG>>>(K);
    k_final  <<<1, 256>>>(out_loss, out_perp, N, K);
}